// round 9
// baseline (speedup 1.0000x reference)
#include <cuda_runtime.h>
#include <cuda_bf16.h>
#include <math.h>
#include <stdint.h>

#define H_   16
#define D_   1024
#define HD_  64
#define PB_  512
#define B_   8
#define N_   512
#define BN_  (B_*N_)          // 4096
#define TWO_PB (2*PB_)        // 1024

// ---------------- scratch (static device arrays: no allocation allowed) ----
__device__ __align__(16) __nv_bfloat16 g_qb[B_*H_*N_*HD_];     // [B,H,N,HD]
__device__ __align__(16) __nv_bfloat16 g_kb[B_*H_*N_*HD_];
__device__ __align__(16) __nv_bfloat16 g_vb[B_*H_*N_*HD_];
__device__ __align__(16) __nv_bfloat16 g_pkb[H_*TWO_PB*HD_];   // [H,2PB,HD]
__device__ __align__(16) __nv_bfloat16 g_pqb[H_*TWO_PB*HD_];
__device__ __align__(16) __nv_bfloat16 g_ctx_bf[BN_*D_];       // [B,N,H,HD]
__device__ float g_h[BN_*D_];                                  // pre-LN residual sum

__device__ __align__(16) __nv_bfloat16 g_hid_bf[BN_*D_];
__device__ __align__(16) __nv_bfloat16 g_rel_bf[TWO_PB*D_];
__device__ __align__(16) __nv_bfloat16 g_wbf[6][D_*D_];        // q,k,v,pk,pq,o (contiguous)

// ============================================================
// helpers (baseline sm_80+: ldmatrix, mma.sync, cp.async)
// ============================================================
__device__ __forceinline__ uint32_t smem_u32(const void* p) {
    uint32_t a;
    asm("{ .reg .u64 t; cvta.to.shared.u64 t, %1; cvt.u32.u64 %0, t; }"
        : "=r"(a) : "l"(p));
    return a;
}
__device__ __forceinline__ void ldsm_x4(uint32_t* r, uint32_t addr) {
    asm volatile("ldmatrix.sync.aligned.m8n8.x4.shared.b16 {%0,%1,%2,%3}, [%4];"
        : "=r"(r[0]), "=r"(r[1]), "=r"(r[2]), "=r"(r[3]) : "r"(addr));
}
__device__ __forceinline__ void ldsm_x4_t(uint32_t* r, uint32_t addr) {
    asm volatile("ldmatrix.sync.aligned.m8n8.x4.trans.shared.b16 {%0,%1,%2,%3}, [%4];"
        : "=r"(r[0]), "=r"(r[1]), "=r"(r[2]), "=r"(r[3]) : "r"(addr));
}
__device__ __forceinline__ void mma16816(float* c, const uint32_t* a, uint32_t b0, uint32_t b1) {
    asm volatile("mma.sync.aligned.m16n8k16.row.col.f32.bf16.bf16.f32 "
        "{%0,%1,%2,%3}, {%4,%5,%6,%7}, {%8,%9}, {%0,%1,%2,%3};"
        : "+f"(c[0]), "+f"(c[1]), "+f"(c[2]), "+f"(c[3])
        : "r"(a[0]), "r"(a[1]), "r"(a[2]), "r"(a[3]), "r"(b0), "r"(b1));
}
#define CP_ASYNC16(dst, src) \
    asm volatile("cp.async.cg.shared.global [%0], [%1], 16;" :: "r"(dst), "l"(src))
#define CP_COMMIT() asm volatile("cp.async.commit_group;" ::: "memory")
#define CP_WAIT0()  asm volatile("cp.async.wait_group 0;" ::: "memory")
#define CP_WAIT1()  asm volatile("cp.async.wait_group 1;" ::: "memory")

#define SWZ(off) ((off) ^ (((off) >> 3) & 0x70))

// ============================================================
// fp32 -> bf16 conversion kernels
// ============================================================
__global__ __launch_bounds__(256) void f2bf(const float* __restrict__ in,
                                            __nv_bfloat16* __restrict__ out, int n) {
    int i = (blockIdx.x * 256 + threadIdx.x) * 4;
    if (i < n) {
        float4 v = *(const float4*)(in + i);
        __nv_bfloat162 lo = __floats2bfloat162_rn(v.x, v.y);
        __nv_bfloat162 hi = __floats2bfloat162_rn(v.z, v.w);
        *(uint2*)(out + i) = make_uint2(*(uint32_t*)&lo, *(uint32_t*)&hi);
    }
}
__global__ __launch_bounds__(256) void f2bf6(
    const float* __restrict__ p0, const float* __restrict__ p1,
    const float* __restrict__ p2, const float* __restrict__ p3,
    const float* __restrict__ p4, const float* __restrict__ p5,
    __nv_bfloat16* __restrict__ out)
{
    const float* ps[6] = {p0, p1, p2, p3, p4, p5};
    const float* in = ps[blockIdx.y];
    int i = (blockIdx.x * 256 + threadIdx.x) * 4;
    float4 v = *(const float4*)(in + i);
    __nv_bfloat162 lo = __floats2bfloat162_rn(v.x, v.y);
    __nv_bfloat162 hi = __floats2bfloat162_rn(v.z, v.w);
    *(uint2*)(out + (size_t)blockIdx.y * D_ * D_ + i) = make_uint2(*(uint32_t*)&lo, *(uint32_t*)&hi);
}

// ============================================================
// shared GEMM mainloop: 128x128 tile, K=1024, 3-stage cp.async.
// A/W pre-offset to their tile origin (row stride D_).
// ============================================================
#define KT 64
#define ABYTES (128*128)
#define STAGEBUF (2*ABYTES)          // A + B per stage = 32KB
#define GEMM_SMEM (3*STAGEBUF)       // 96KB

__device__ __forceinline__ void gemm_core(
    const __nv_bfloat16* __restrict__ A, const __nv_bfloat16* __restrict__ W,
    uint32_t sbase, int tid, int lane, int wm, int wn, float acc[2][8][4])
{
    #pragma unroll
    for (int i = 0; i < 2; i++)
        #pragma unroll
        for (int j = 0; j < 8; j++)
            #pragma unroll
            for (int l = 0; l < 4; l++) acc[i][j][l] = 0.0f;

    auto load_tile = [&](int kt, int stage) {
        const __nv_bfloat16* Ap = A + kt * KT;
        const __nv_bfloat16* Wp = W + kt * KT;
        uint32_t da = sbase + stage * STAGEBUF;
        uint32_t db = da + ABYTES;
        #pragma unroll
        for (int i = 0; i < 4; i++) {
            int c = i * 256 + tid;
            int r = c >> 3, k8 = c & 7;
            uint32_t off = SWZ((uint32_t)(r * 128 + k8 * 16));
            CP_ASYNC16(da + off, Ap + (size_t)r * D_ + k8 * 8);
            CP_ASYNC16(db + off, Wp + (size_t)r * D_ + k8 * 8);
        }
    };

    load_tile(0, 0); CP_COMMIT();
    load_tile(1, 1); CP_COMMIT();

    const int matm = lane >> 3, rin = lane & 7;
    int stage = 0;
    for (int kt = 0; kt < 16; kt++) {
        if (kt == 15) CP_WAIT0(); else CP_WAIT1();
        __syncthreads();
        if (kt + 2 < 16) {
            int ns = stage + 2; if (ns >= 3) ns -= 3;
            load_tile(kt + 2, ns);
            CP_COMMIT();
        }
        uint32_t abase = sbase + stage * STAGEBUF;
        uint32_t bbase = abase + ABYTES;
        #pragma unroll
        for (int ks = 0; ks < 4; ks++) {
            uint32_t af[2][4], bfr[4][4];
            int kcol = ks * 16 + (matm >> 1) * 8;
            #pragma unroll
            for (int mt = 0; mt < 2; mt++) {
                int m = wm + mt * 16 + (matm & 1) * 8 + rin;
                ldsm_x4(af[mt], abase + SWZ((uint32_t)(m * 128 + kcol * 2)));
            }
            #pragma unroll
            for (int u = 0; u < 4; u++) {
                int n = wn + u * 16 + (matm & 1) * 8 + rin;
                ldsm_x4(bfr[u], bbase + SWZ((uint32_t)(n * 128 + kcol * 2)));
            }
            #pragma unroll
            for (int mt = 0; mt < 2; mt++)
                #pragma unroll
                for (int nt = 0; nt < 8; nt++) {
                    int u = nt >> 1, w = nt & 1;
                    mma16816(acc[mt][nt], af[mt], bfr[u][w], bfr[u][w + 2]);
                }
        }
        stage++; if (stage >= 3) stage -= 3;
    }
}

// ============================================================
// Combined QKV + pos projection launch. grid (40, 32):
//   x<24           : QKV block (fused N=3072), bm = y*128 over BN
//   x>=24 && y<8   : pos block (fused N=2048), bm = y*128 over 2PB
//   else           : exit
// ============================================================
__global__ __launch_bounds__(256) void gemm_qkvpos(
    const __nv_bfloat16* __restrict__ hid, const __nv_bfloat16* __restrict__ rel,
    const __nv_bfloat16* __restrict__ wq,
    const float* __restrict__ q_b, const float* __restrict__ k_b,
    const float* __restrict__ v_b, const float* __restrict__ pk_b,
    const float* __restrict__ pq_b)
{
    const int x = blockIdx.x, y = blockIdx.y;
    int qkv = (x < 24);
    if (!qkv && y >= 8) return;

    extern __shared__ char smch[];
    const uint32_t sbase = smem_u32(smch);
    const int tid = threadIdx.x, warp = tid >> 5, lane = tid & 31;
    const int wm = (warp >> 1) * 32, wn = (warp & 1) * 64;

    const int bn = qkv ? x * 128 : (x - 24) * 128;
    const int bm = y * 128;
    const __nv_bfloat16* A = (qkv ? hid : rel) + (size_t)bm * D_;
    const __nv_bfloat16* W = wq + (qkv ? 0ull : 3ull * D_ * D_) + (size_t)bn * D_;

    float acc[2][8][4];
    gemm_core(A, W, sbase, tid, lane, wm, wn, acc);

    const int g = lane >> 2, tg = lane & 3;
    const int t = bn >> 10;
    const float* bias;
    __nv_bfloat16* outbf;
    if (qkv) {
        bias = (t == 0) ? q_b : ((t == 1) ? k_b : v_b);
        outbf = (t == 0) ? g_qb : ((t == 1) ? g_kb : g_vb);
    } else {
        bias = (t == 0) ? pk_b : pq_b;
        outbf = (t == 0) ? g_pkb : g_pqb;
    }

    #pragma unroll
    for (int mt = 0; mt < 2; mt++) {
        #pragma unroll
        for (int nt = 0; nt < 8; nt++) {
            int col = bn + wn + nt * 8 + tg * 2;
            int cn = col & 1023;
            float bb0 = bias[cn], bb1 = bias[cn + 1];
            int h = cn >> 6, hd = cn & 63;
            #pragma unroll
            for (int half = 0; half < 2; half++) {
                int m = bm + wm + mt * 16 + g + half * 8;
                float v0 = acc[mt][nt][half * 2 + 0] + bb0;
                float v1 = acc[mt][nt][half * 2 + 1] + bb1;
                __nv_bfloat162 pk2 = __floats2bfloat162_rn(v0, v1);
                size_t idx;
                if (qkv) {
                    int bb = m >> 9, n = m & 511;
                    idx = (((size_t)(bb * H_ + h)) * N_ + n) * HD_ + hd;
                } else {
                    idx = ((size_t)h * TWO_PB + m) * HD_ + hd;
                }
                *(__nv_bfloat162*)&outbf[idx] = pk2;
            }
        }
    }
}

// ============================================================
// O-projection + bias + residual (fp32 out)
// ============================================================
__global__ __launch_bounds__(256) void gemm_o(
    const __nv_bfloat16* __restrict__ A, const __nv_bfloat16* __restrict__ W,
    const float* __restrict__ bias, const float* __restrict__ resid,
    float* __restrict__ outf)
{
    extern __shared__ char smch[];
    const uint32_t sbase = smem_u32(smch);
    const int tid = threadIdx.x, warp = tid >> 5, lane = tid & 31;
    const int wm = (warp >> 1) * 32, wn = (warp & 1) * 64;
    const int bm = blockIdx.y * 128, bn = blockIdx.x * 128;

    float acc[2][8][4];
    gemm_core(A + (size_t)bm * D_, W + (size_t)bn * D_, sbase, tid, lane, wm, wn, acc);

    const int g = lane >> 2, tg = lane & 3;
    #pragma unroll
    for (int mt = 0; mt < 2; mt++) {
        #pragma unroll
        for (int nt = 0; nt < 8; nt++) {
            int col = bn + wn + nt * 8 + tg * 2;
            float bb0 = bias[col], bb1 = bias[col + 1];
            #pragma unroll
            for (int half = 0; half < 2; half++) {
                int m = bm + wm + mt * 16 + g + half * 8;
                float v0 = acc[mt][nt][half * 2 + 0] + bb0;
                float v1 = acc[mt][nt][half * 2 + 1] + bb1;
                size_t idx = (size_t)m * D_ + col;
                float2 r = *(const float2*)&resid[idx];
                *(float2*)&outf[idx] = make_float2(v0 + r.x, v1 + r.y);
            }
        }
    }
}

// ============================================================
// Tensorized disentangled flash attention, pipelined loads.
// grid (N/64, B*H), 128 threads. K/V double-buffered; pos prefetched
// mid-iteration (phase 1 is its last reader).
// ============================================================
#define BAND_STRIDE 264
#define A2_SQ   0
#define A2_SK   8192                    // 2 x 8KB
#define A2_SV   24576                   // 2 x 8KB
#define A2_SPK  40960                   // 16KB
#define A2_SPQ  57344                   // 16KB
#define A2_SC   73728                   // band 64 x 264
#define A2_SP   (A2_SC + 64*BAND_STRIDE)
#define A2_SMEM (A2_SP + 64*BAND_STRIDE)   // 107520 B

__global__ __launch_bounds__(128) void attn_mma(
    const __nv_bfloat16* __restrict__ q, const __nv_bfloat16* __restrict__ k,
    const __nv_bfloat16* __restrict__ v, const __nv_bfloat16* __restrict__ posk,
    const __nv_bfloat16* __restrict__ posq, __nv_bfloat16* __restrict__ ctx)
{
    extern __shared__ char smch[];
    const uint32_t sb = smem_u32(smch);
    const uint32_t sQ = sb + A2_SQ;
    const uint32_t sPK = sb + A2_SPK, sPQ = sb + A2_SPQ;
    const uint32_t sC = sb + A2_SC, sP = sb + A2_SP;

    const int tid = threadIdx.x, warp = tid >> 5, lane = tid & 31;
    const int g = lane >> 2, tg = lane & 3;
    const int matm = lane >> 3, rin = lane & 7;
    const int wm = warp * 16;
    const int i0 = blockIdx.x * 64;
    const int bh = blockIdx.y;
    const int h = bh & (H_ - 1);

    const __nv_bfloat16* qb  = q + ((size_t)bh * N_ + i0) * HD_;
    const __nv_bfloat16* kb  = k + (size_t)bh * N_ * HD_;
    const __nv_bfloat16* vb  = v + (size_t)bh * N_ * HD_;
    const __nv_bfloat16* pkb = posk + (size_t)h * TWO_PB * HD_;
    const __nv_bfloat16* pqb = posq + (size_t)h * TWO_PB * HD_;

    auto load_kv = [&](int j0, int p) {
        uint32_t dk = sb + A2_SK + p * 8192;
        uint32_t dv = sb + A2_SV + p * 8192;
        #pragma unroll
        for (int it = 0; it < 4; it++) {
            int c = it * 128 + tid, r = c >> 3, k8 = c & 7;
            uint32_t off = SWZ((uint32_t)(r * 128 + k8 * 16));
            CP_ASYNC16(dk + off, kb + (size_t)(j0 + r) * HD_ + k8 * 8);
            CP_ASYNC16(dv + off, vb + (size_t)(j0 + r) * HD_ + k8 * 8);
        }
    };
    auto load_pos = [&](int base) {
        #pragma unroll
        for (int it = 0; it < 8; it++) {
            int c = it * 128 + tid, r = c >> 3, k8 = c & 7;
            int sr = base + r; if (sr > 1023) sr = 1023;   // row 127 unused pad
            uint32_t off = SWZ((uint32_t)(r * 128 + k8 * 16));
            CP_ASYNC16(sPK + off, pkb + (size_t)sr * HD_ + k8 * 8);
            CP_ASYNC16(sPQ + off, pqb + (size_t)sr * HD_ + k8 * 8);
        }
    };

    // prologue: Q + first K/V + first pos, one group
    #pragma unroll
    for (int it = 0; it < 4; it++) {
        int c = it * 128 + tid, r = c >> 3, k8 = c & 7;
        CP_ASYNC16(sQ + SWZ((uint32_t)(r * 128 + k8 * 16)), qb + r * HD_ + k8 * 8);
    }
    load_kv(0, 0);
    load_pos(i0 + PB_ - 63);
    CP_COMMIT();

    float m0 = -INFINITY, m1 = -INFINITY, l0 = 0.f, l1 = 0.f;
    float opv[8][4];
    #pragma unroll
    for (int i = 0; i < 8; i++)
        #pragma unroll
        for (int e = 0; e < 4; e++) opv[i][e] = 0.f;
    const float inv_scale = 0.0721687836f;     // 1/sqrt(192)

    for (int jt = 0; jt < 8; jt++) {
        const int j0 = jt * 64;
        const int p = jt & 1;
        const uint32_t sKp = sb + A2_SK + p * 8192;
        const uint32_t sVp = sb + A2_SV + p * 8192;

        CP_WAIT0();
        __syncthreads();                       // loads for jt landed; prev iter fully done
        if (jt < 7) { load_kv(j0 + 64, p ^ 1); CP_COMMIT(); }

        // phase 1: band GEMMs C2P = Q.PKwin^T, P2C = K.PQwin^T
        #pragma unroll
        for (int ph = 0; ph < 2; ph++) {
            uint32_t aSrc = ph ? sKp : sQ;
            uint32_t bSrc = ph ? sPQ : sPK;
            uint32_t dSt  = ph ? sP : sC;
            float t[16][4];
            #pragma unroll
            for (int i = 0; i < 16; i++)
                #pragma unroll
                for (int e = 0; e < 4; e++) t[i][e] = 0.f;
            #pragma unroll
            for (int ks = 0; ks < 4; ks++) {
                uint32_t af[4];
                int ar = wm + (matm & 1) * 8 + rin, kc = ks * 16 + (matm >> 1) * 8;
                ldsm_x4(af, aSrc + SWZ((uint32_t)(ar * 128 + kc * 2)));
                #pragma unroll
                for (int u = 0; u < 8; u++) {
                    uint32_t bf4[4];
                    int nr = u * 16 + (matm & 1) * 8 + rin;
                    ldsm_x4(bf4, bSrc + SWZ((uint32_t)(nr * 128 + kc * 2)));
                    mma16816(t[2 * u],     af, bf4[0], bf4[2]);
                    mma16816(t[2 * u + 1], af, bf4[1], bf4[3]);
                }
            }
            #pragma unroll
            for (int nt = 0; nt < 16; nt++) {
                int col = nt * 8 + tg * 2;
                __nv_bfloat162 lo = __floats2bfloat162_rn(t[nt][0], t[nt][1]);
                __nv_bfloat162 hi = __floats2bfloat162_rn(t[nt][2], t[nt][3]);
                uint32_t a0 = dSt + (wm + g) * BAND_STRIDE + col * 2;
                uint32_t a1 = dSt + (wm + g + 8) * BAND_STRIDE + col * 2;
                asm volatile("st.shared.b32 [%0], %1;" :: "r"(a0), "r"(*(uint32_t*)&lo));
                asm volatile("st.shared.b32 [%0], %1;" :: "r"(a1), "r"(*(uint32_t*)&hi));
            }
        }
        __syncthreads();                       // bands visible; pos fully consumed
        if (jt < 7) { load_pos(i0 - (j0 + 64) + PB_ - 63); CP_COMMIT(); }

        // phase 2: S = Q.K^T + band gather, online softmax
        float s[8][4];
        #pragma unroll
        for (int i = 0; i < 8; i++)
            #pragma unroll
            for (int e = 0; e < 4; e++) s[i][e] = 0.f;
        #pragma unroll
        for (int ks = 0; ks < 4; ks++) {
            uint32_t af[4];
            int ar = wm + (matm & 1) * 8 + rin, kc = ks * 16 + (matm >> 1) * 8;
            ldsm_x4(af, sQ + SWZ((uint32_t)(ar * 128 + kc * 2)));
            #pragma unroll
            for (int u = 0; u < 4; u++) {
                uint32_t bf4[4];
                int nr = u * 16 + (matm & 1) * 8 + rin;
                ldsm_x4(bf4, sKp + SWZ((uint32_t)(nr * 128 + kc * 2)));
                mma16816(s[2 * u],     af, bf4[0], bf4[2]);
                mma16816(s[2 * u + 1], af, bf4[1], bf4[3]);
            }
        }
        #pragma unroll
        for (int nt = 0; nt < 8; nt++) {
            #pragma unroll
            for (int e = 0; e < 4; e++) {
                int di = wm + g + (e >> 1) * 8;
                int dj = nt * 8 + tg * 2 + (e & 1);
                int w = di - dj + 63;
                uint16_t cv, pv2;
                asm volatile("ld.shared.u16 %0, [%1];" : "=h"(cv)
                             : "r"(sC + di * BAND_STRIDE + w * 2));
                asm volatile("ld.shared.u16 %0, [%1];" : "=h"(pv2)
                             : "r"(sP + dj * BAND_STRIDE + w * 2));
                float add = __bfloat162float(*(__nv_bfloat16*)&cv)
                          + __bfloat162float(*(__nv_bfloat16*)&pv2);
                s[nt][e] = (s[nt][e] + add) * inv_scale;
            }
        }
        float mx0 = -INFINITY, mx1 = -INFINITY;
        #pragma unroll
        for (int nt = 0; nt < 8; nt++) {
            mx0 = fmaxf(mx0, fmaxf(s[nt][0], s[nt][1]));
            mx1 = fmaxf(mx1, fmaxf(s[nt][2], s[nt][3]));
        }
        mx0 = fmaxf(mx0, __shfl_xor_sync(0xFFFFFFFF, mx0, 1));
        mx0 = fmaxf(mx0, __shfl_xor_sync(0xFFFFFFFF, mx0, 2));
        mx1 = fmaxf(mx1, __shfl_xor_sync(0xFFFFFFFF, mx1, 1));
        mx1 = fmaxf(mx1, __shfl_xor_sync(0xFFFFFFFF, mx1, 2));
        float mn0 = fmaxf(m0, mx0), mn1 = fmaxf(m1, mx1);
        float sc0 = __expf(m0 - mn0), sc1 = __expf(m1 - mn1);
        m0 = mn0; m1 = mn1;
        float sum0 = 0.f, sum1 = 0.f;
        #pragma unroll
        for (int nt = 0; nt < 8; nt++) {
            #pragma unroll
            for (int e = 0; e < 4; e++) {
                float pr = __expf(s[nt][e] - ((e < 2) ? mn0 : mn1));
                s[nt][e] = pr;
                if (e < 2) sum0 += pr; else sum1 += pr;
            }
        }
        sum0 += __shfl_xor_sync(0xFFFFFFFF, sum0, 1);
        sum0 += __shfl_xor_sync(0xFFFFFFFF, sum0, 2);
        sum1 += __shfl_xor_sync(0xFFFFFFFF, sum1, 1);
        sum1 += __shfl_xor_sync(0xFFFFFFFF, sum1, 2);
        l0 = l0 * sc0 + sum0;
        l1 = l1 * sc1 + sum1;
        #pragma unroll
        for (int nt = 0; nt < 8; nt++) {
            opv[nt][0] *= sc0; opv[nt][1] *= sc0;
            opv[nt][2] *= sc1; opv[nt][3] *= sc1;
        }
        // PV: P (bf16 fragments) @ V via ldmatrix.trans
        #pragma unroll
        for (int kk = 0; kk < 4; kk++) {
            uint32_t aP[4];
            __nv_bfloat162 t0 = __floats2bfloat162_rn(s[2*kk][0],   s[2*kk][1]);
            __nv_bfloat162 t1 = __floats2bfloat162_rn(s[2*kk][2],   s[2*kk][3]);
            __nv_bfloat162 t2 = __floats2bfloat162_rn(s[2*kk+1][0], s[2*kk+1][1]);
            __nv_bfloat162 t3 = __floats2bfloat162_rn(s[2*kk+1][2], s[2*kk+1][3]);
            aP[0] = *(uint32_t*)&t0; aP[1] = *(uint32_t*)&t1;
            aP[2] = *(uint32_t*)&t2; aP[3] = *(uint32_t*)&t3;
            int jb = kk * 16;
            #pragma unroll
            for (int du = 0; du < 4; du++) {
                uint32_t bv[4];
                int vr = jb + (matm & 1) * 8 + rin, vc = du * 16 + (matm >> 1) * 8;
                ldsm_x4_t(bv, sVp + SWZ((uint32_t)(vr * 128 + vc * 2)));
                mma16816(opv[2 * du],     aP, bv[0], bv[1]);
                mma16816(opv[2 * du + 1], aP, bv[2], bv[3]);
            }
        }
        // no end-of-loop sync: top-of-loop barrier protects all reuse
    }

    const int b = bh >> 4;
    float il0 = 1.0f / l0, il1 = 1.0f / l1;
    int row0 = i0 + wm + g, row1 = row0 + 8;
    #pragma unroll
    for (int nt = 0; nt < 8; nt++) {
        int d = nt * 8 + tg * 2;
        __nv_bfloat162 o0 = __floats2bfloat162_rn(opv[nt][0] * il0, opv[nt][1] * il0);
        __nv_bfloat162 o1 = __floats2bfloat162_rn(opv[nt][2] * il1, opv[nt][3] * il1);
        *(__nv_bfloat162*)&ctx[(((size_t)b * N_ + row0) * H_ + h) * HD_ + d] = o0;
        *(__nv_bfloat162*)&ctx[(((size_t)b * N_ + row1) * H_ + h) * HD_ + d] = o1;
    }
}

// ---------------------------------------------------------------------------
// Row LayerNorm
// ---------------------------------------------------------------------------
__global__ __launch_bounds__(256) void ln_kernel(
    const float* __restrict__ hb, const float* __restrict__ gam,
    const float* __restrict__ bet, float* __restrict__ out)
{
    const int row = blockIdx.x, tid = threadIdx.x;
    const float* hr = hb + (size_t)row * D_;
    __shared__ float red[256];

    float lv[4];
    float s = 0.0f;
    #pragma unroll
    for (int i = 0; i < 4; i++) { lv[i] = hr[i*256 + tid]; s += lv[i]; }
    red[tid] = s; __syncthreads();
    #pragma unroll
    for (int o = 128; o > 0; o >>= 1) { if (tid < o) red[tid] += red[tid + o]; __syncthreads(); }
    float mu = red[0] * (1.0f / 1024.0f);
    __syncthreads();

    float s2 = 0.0f;
    #pragma unroll
    for (int i = 0; i < 4; i++) { float dv = lv[i] - mu; s2 += dv * dv; }
    red[tid] = s2; __syncthreads();
    #pragma unroll
    for (int o = 128; o > 0; o >>= 1) { if (tid < o) red[tid] += red[tid + o]; __syncthreads(); }
    float var = red[0] * (1.0f / 1024.0f);
    float inv = rsqrtf(var + 1e-7f);

    #pragma unroll
    for (int i = 0; i < 4; i++) {
        int c = i*256 + tid;
        out[(size_t)row * D_ + c] = (lv[i] - mu) * inv * gam[c] + bet[c];
    }
}

// ---------------------------------------------------------------------------
extern "C" void kernel_launch(void* const* d_in, const int* in_sizes, int n_in,
                              void* d_out, int out_size)
{
    const float* hidden = (const float*)d_in[0];
    const float* rel    = (const float*)d_in[1];
    const float* q_w = (const float*)d_in[2];  const float* q_b = (const float*)d_in[3];
    const float* k_w = (const float*)d_in[4];  const float* k_b = (const float*)d_in[5];
    const float* v_w = (const float*)d_in[6];  const float* v_b = (const float*)d_in[7];
    const float* pk_w = (const float*)d_in[8]; const float* pk_b = (const float*)d_in[9];
    const float* pq_w = (const float*)d_in[10];const float* pq_b = (const float*)d_in[11];
    const float* o_w = (const float*)d_in[12]; const float* o_b = (const float*)d_in[13];
    const float* ln_g = (const float*)d_in[14];const float* ln_b = (const float*)d_in[15];

    __nv_bfloat16 *pqb, *pkb, *pvb, *ppk, *ppq, *pctxbf, *phidbf, *prelbf, *pwbf;
    float *ph;
    cudaGetSymbolAddress((void**)&pqb,  g_qb);
    cudaGetSymbolAddress((void**)&pkb,  g_kb);
    cudaGetSymbolAddress((void**)&pvb,  g_vb);
    cudaGetSymbolAddress((void**)&ppk,  g_pkb);
    cudaGetSymbolAddress((void**)&ppq,  g_pqb);
    cudaGetSymbolAddress((void**)&pctxbf, g_ctx_bf);
    cudaGetSymbolAddress((void**)&ph,   g_h);
    cudaGetSymbolAddress((void**)&phidbf, g_hid_bf);
    cudaGetSymbolAddress((void**)&prelbf, g_rel_bf);
    cudaGetSymbolAddress((void**)&pwbf,   g_wbf);

    __nv_bfloat16* wq = pwbf;                     // fused QKV base (pos at +3*D*D)
    __nv_bfloat16* wo = pwbf + 5ull * D_ * D_;

    cudaFuncSetAttribute(gemm_qkvpos, cudaFuncAttributeMaxDynamicSharedMemorySize, GEMM_SMEM);
    cudaFuncSetAttribute(gemm_o, cudaFuncAttributeMaxDynamicSharedMemorySize, GEMM_SMEM);
    cudaFuncSetAttribute(attn_mma, cudaFuncAttributeMaxDynamicSharedMemorySize, A2_SMEM);

    // fp32 -> bf16 conversions
    f2bf<<<BN_*D_/1024, 256>>>(hidden, phidbf, BN_*D_);
    f2bf<<<TWO_PB*D_/1024, 256>>>(rel, prelbf, TWO_PB*D_);
    f2bf6<<<dim3(D_*D_/1024, 6), 256>>>(q_w, k_w, v_w, pk_w, pq_w, o_w, pwbf);

    // combined QKV + pos projections: one launch
    gemm_qkvpos<<<dim3(40, 32), 256, GEMM_SMEM>>>(
        phidbf, prelbf, wq, q_b, k_b, v_b, pk_b, pq_b);

    // tensorized disentangled flash attention -> bf16 ctx
    attn_mma<<<dim3(N_/64, B_*H_), 128, A2_SMEM>>>(pqb, pkb, pvb, ppk, ppq, pctxbf);

    // output projection + bias + residual (fp32 out)
    gemm_o<<<dim3(D_/128, BN_/128), 256, GEMM_SMEM>>>(pctxbf, wo, o_b, hidden, ph);

    // layernorm -> final output
    ln_kernel<<<BN_, 256>>>(ph, ln_g, ln_b, (float*)d_out);
}

// round 11
// speedup vs baseline: 1.0350x; 1.0350x over previous
#include <cuda_runtime.h>
#include <cuda_bf16.h>
#include <math.h>
#include <stdint.h>

#define H_   16
#define D_   1024
#define HD_  64
#define PB_  512
#define B_   8
#define N_   512
#define BN_  (B_*N_)          // 4096
#define TWO_PB (2*PB_)        // 1024

// ---------------- scratch (static device arrays: no allocation allowed) ----
__device__ __align__(16) __nv_bfloat16 g_qb[B_*H_*N_*HD_];     // [B,H,N,HD]
__device__ __align__(16) __nv_bfloat16 g_kb[B_*H_*N_*HD_];
__device__ __align__(16) __nv_bfloat16 g_vb[B_*H_*N_*HD_];
__device__ __align__(16) __nv_bfloat16 g_pkb[H_*TWO_PB*HD_];   // [H,2PB,HD]
__device__ __align__(16) __nv_bfloat16 g_pqb[H_*TWO_PB*HD_];
__device__ __align__(16) __nv_bfloat16 g_ctx_bf[BN_*D_];       // [B,N,H,HD]
__device__ float g_h[BN_*D_];                                  // pre-LN residual sum

__device__ __align__(16) __nv_bfloat16 g_hid_bf[BN_*D_];
__device__ __align__(16) __nv_bfloat16 g_rel_bf[TWO_PB*D_];
__device__ __align__(16) __nv_bfloat16 g_wbf[6][D_*D_];        // q,k,v,pk,pq,o (contiguous)

// ============================================================
// helpers (baseline sm_80+: ldmatrix, mma.sync, cp.async)
// ============================================================
__device__ __forceinline__ uint32_t smem_u32(const void* p) {
    uint32_t a;
    asm("{ .reg .u64 t; cvta.to.shared.u64 t, %1; cvt.u32.u64 %0, t; }"
        : "=r"(a) : "l"(p));
    return a;
}
__device__ __forceinline__ void ldsm_x4(uint32_t* r, uint32_t addr) {
    asm volatile("ldmatrix.sync.aligned.m8n8.x4.shared.b16 {%0,%1,%2,%3}, [%4];"
        : "=r"(r[0]), "=r"(r[1]), "=r"(r[2]), "=r"(r[3]) : "r"(addr));
}
__device__ __forceinline__ void ldsm_x4_t(uint32_t* r, uint32_t addr) {
    asm volatile("ldmatrix.sync.aligned.m8n8.x4.trans.shared.b16 {%0,%1,%2,%3}, [%4];"
        : "=r"(r[0]), "=r"(r[1]), "=r"(r[2]), "=r"(r[3]) : "r"(addr));
}
__device__ __forceinline__ void mma16816(float* c, const uint32_t* a, uint32_t b0, uint32_t b1) {
    asm volatile("mma.sync.aligned.m16n8k16.row.col.f32.bf16.bf16.f32 "
        "{%0,%1,%2,%3}, {%4,%5,%6,%7}, {%8,%9}, {%0,%1,%2,%3};"
        : "+f"(c[0]), "+f"(c[1]), "+f"(c[2]), "+f"(c[3])
        : "r"(a[0]), "r"(a[1]), "r"(a[2]), "r"(a[3]), "r"(b0), "r"(b1));
}
#define CP_ASYNC16(dst, src) \
    asm volatile("cp.async.cg.shared.global [%0], [%1], 16;" :: "r"(dst), "l"(src))
#define CP_COMMIT() asm volatile("cp.async.commit_group;" ::: "memory")
#define CP_WAIT0()  asm volatile("cp.async.wait_group 0;" ::: "memory")
#define CP_WAIT1()  asm volatile("cp.async.wait_group 1;" ::: "memory")

#define SWZ(off) ((off) ^ (((off) >> 3) & 0x70))

// ============================================================
// fp32 -> bf16 conversion kernels
// ============================================================
__global__ __launch_bounds__(256) void f2bf(const float* __restrict__ in,
                                            __nv_bfloat16* __restrict__ out, int n) {
    int i = (blockIdx.x * 256 + threadIdx.x) * 4;
    if (i < n) {
        float4 v = *(const float4*)(in + i);
        __nv_bfloat162 lo = __floats2bfloat162_rn(v.x, v.y);
        __nv_bfloat162 hi = __floats2bfloat162_rn(v.z, v.w);
        *(uint2*)(out + i) = make_uint2(*(uint32_t*)&lo, *(uint32_t*)&hi);
    }
}
__global__ __launch_bounds__(256) void f2bf6(
    const float* __restrict__ p0, const float* __restrict__ p1,
    const float* __restrict__ p2, const float* __restrict__ p3,
    const float* __restrict__ p4, const float* __restrict__ p5,
    __nv_bfloat16* __restrict__ out)
{
    const float* ps[6] = {p0, p1, p2, p3, p4, p5};
    const float* in = ps[blockIdx.y];
    int i = (blockIdx.x * 256 + threadIdx.x) * 4;
    float4 v = *(const float4*)(in + i);
    __nv_bfloat162 lo = __floats2bfloat162_rn(v.x, v.y);
    __nv_bfloat162 hi = __floats2bfloat162_rn(v.z, v.w);
    *(uint2*)(out + (size_t)blockIdx.y * D_ * D_ + i) = make_uint2(*(uint32_t*)&lo, *(uint32_t*)&hi);
}

// ============================================================
// mma.sync bf16 NT GEMM, 3-stage cp.async pipeline (R8 proven: 127 regs).
// out[m,c] = sum_k A[m,k]*W[c,k] + bias[c]; CTA tile 128x128, K-tile 64.
// mode 1: fused QKV (W rows [0,3072), t=bn>>10 selects g_qb/g_kb/g_vb + bias)
// mode 0: fused pos (W rows [0,2048), t selects g_pkb/g_pqb)
// mode 2: O proj + residual (fp32 out)
// ============================================================
#define KT 64
#define ABYTES (128*128)
#define STAGEBUF (2*ABYTES)          // A + B per stage = 32KB
#define GEMM_SMEM (3*STAGEBUF)       // 96KB

__global__ __launch_bounds__(256, 2) void gemm_mma(
    const __nv_bfloat16* __restrict__ A, const __nv_bfloat16* __restrict__ W,
    const float* __restrict__ b0p, const float* __restrict__ b1p,
    const float* __restrict__ b2p, const float* __restrict__ resid,
    float* __restrict__ outf, int mode)
{
    extern __shared__ char smch[];
    const uint32_t sbase = smem_u32(smch);
    const int tid = threadIdx.x, warp = tid >> 5, lane = tid & 31;
    const int bm = blockIdx.y * 128, bn = blockIdx.x * 128;
    const int wm = (warp >> 1) * 32, wn = (warp & 1) * 64;

    float acc[2][8][4];
    #pragma unroll
    for (int i = 0; i < 2; i++)
        #pragma unroll
        for (int j = 0; j < 8; j++)
            #pragma unroll
            for (int l = 0; l < 4; l++) acc[i][j][l] = 0.0f;

    auto load_tile = [&](int kt, int stage) {
        const __nv_bfloat16* Ap = A + (size_t)bm * D_ + kt * KT;
        const __nv_bfloat16* Wp = W + (size_t)bn * D_ + kt * KT;
        uint32_t da = sbase + stage * STAGEBUF;
        uint32_t db = da + ABYTES;
        #pragma unroll
        for (int i = 0; i < 4; i++) {
            int c = i * 256 + tid;
            int r = c >> 3, k8 = c & 7;
            uint32_t off = SWZ((uint32_t)(r * 128 + k8 * 16));
            CP_ASYNC16(da + off, Ap + (size_t)r * D_ + k8 * 8);
            CP_ASYNC16(db + off, Wp + (size_t)r * D_ + k8 * 8);
        }
    };

    load_tile(0, 0); CP_COMMIT();
    load_tile(1, 1); CP_COMMIT();

    const int matm = lane >> 3, rin = lane & 7;
    int stage = 0;
    for (int kt = 0; kt < 16; kt++) {
        if (kt == 15) CP_WAIT0(); else CP_WAIT1();
        __syncthreads();
        if (kt + 2 < 16) {
            int ns = stage + 2; if (ns >= 3) ns -= 3;
            load_tile(kt + 2, ns);
            CP_COMMIT();
        }
        uint32_t abase = sbase + stage * STAGEBUF;
        uint32_t bbase = abase + ABYTES;
        #pragma unroll
        for (int ks = 0; ks < 4; ks++) {
            uint32_t af[2][4], bfr[4][4];
            int kcol = ks * 16 + (matm >> 1) * 8;
            #pragma unroll
            for (int mt = 0; mt < 2; mt++) {
                int m = wm + mt * 16 + (matm & 1) * 8 + rin;
                ldsm_x4(af[mt], abase + SWZ((uint32_t)(m * 128 + kcol * 2)));
            }
            #pragma unroll
            for (int u = 0; u < 4; u++) {
                int n = wn + u * 16 + (matm & 1) * 8 + rin;
                ldsm_x4(bfr[u], bbase + SWZ((uint32_t)(n * 128 + kcol * 2)));
            }
            #pragma unroll
            for (int mt = 0; mt < 2; mt++)
                #pragma unroll
                for (int nt = 0; nt < 8; nt++) {
                    int u = nt >> 1, w = nt & 1;
                    mma16816(acc[mt][nt], af[mt], bfr[u][w], bfr[u][w + 2]);
                }
        }
        stage++; if (stage >= 3) stage -= 3;
    }

    // ---- epilogue ----
    const int g = lane >> 2, tg = lane & 3;
    const int t = bn >> 10;                         // which tensor (fused modes)
    const float* bias = (t == 0) ? b0p : ((t == 1) ? b1p : b2p);
    __nv_bfloat16* outbf = nullptr;
    if (mode == 1) outbf = (t == 0) ? g_qb : ((t == 1) ? g_kb : g_vb);
    else if (mode == 0) outbf = (t == 0) ? g_pkb : g_pqb;

    #pragma unroll
    for (int mt = 0; mt < 2; mt++) {
        #pragma unroll
        for (int nt = 0; nt < 8; nt++) {
            int col = bn + wn + nt * 8 + tg * 2;     // global col in fused N
            int cn = col & 1023;                      // col within tensor
            float bb0 = bias[cn], bb1 = bias[cn + 1];
            #pragma unroll
            for (int half = 0; half < 2; half++) {
                int m = bm + wm + mt * 16 + g + half * 8;
                float v0 = acc[mt][nt][half * 2 + 0] + bb0;
                float v1 = acc[mt][nt][half * 2 + 1] + bb1;
                if (mode == 2) {
                    size_t idx = (size_t)m * D_ + cn;
                    float2 r = *(const float2*)&resid[idx];
                    *(float2*)&outf[idx] = make_float2(v0 + r.x, v1 + r.y);
                } else {
                    __nv_bfloat162 pk2 = __floats2bfloat162_rn(v0, v1);
                    size_t idx;
                    int h = cn >> 6, hd = cn & 63;
                    if (mode == 1) {
                        int bb = m >> 9, n = m & 511;
                        idx = (((size_t)(bb * H_ + h)) * N_ + n) * HD_ + hd;
                    } else {
                        idx = ((size_t)h * TWO_PB + m) * HD_ + hd;
                    }
                    *(__nv_bfloat162*)&outbf[idx] = pk2;
                }
            }
        }
    }
}

// ============================================================
// Tensorized disentangled flash attention, pipelined loads (R9).
// grid (N/64, B*H), 128 threads. K/V double-buffered; pos prefetched
// mid-iteration (phase 1 is its last reader).
// ============================================================
#define BAND_STRIDE 264
#define A2_SQ   0
#define A2_SK   8192                    // 2 x 8KB
#define A2_SV   24576                   // 2 x 8KB
#define A2_SPK  40960                   // 16KB
#define A2_SPQ  57344                   // 16KB
#define A2_SC   73728                   // band 64 x 264
#define A2_SP   (A2_SC + 64*BAND_STRIDE)
#define A2_SMEM (A2_SP + 64*BAND_STRIDE)   // 107520 B

__global__ __launch_bounds__(128) void attn_mma(
    const __nv_bfloat16* __restrict__ q, const __nv_bfloat16* __restrict__ k,
    const __nv_bfloat16* __restrict__ v, const __nv_bfloat16* __restrict__ posk,
    const __nv_bfloat16* __restrict__ posq, __nv_bfloat16* __restrict__ ctx)
{
    extern __shared__ char smch[];
    const uint32_t sb = smem_u32(smch);
    const uint32_t sQ = sb + A2_SQ;
    const uint32_t sPK = sb + A2_SPK, sPQ = sb + A2_SPQ;
    const uint32_t sC = sb + A2_SC, sP = sb + A2_SP;

    const int tid = threadIdx.x, warp = tid >> 5, lane = tid & 31;
    const int g = lane >> 2, tg = lane & 3;
    const int matm = lane >> 3, rin = lane & 7;
    const int wm = warp * 16;
    const int i0 = blockIdx.x * 64;
    const int bh = blockIdx.y;
    const int h = bh & (H_ - 1);

    const __nv_bfloat16* qb  = q + ((size_t)bh * N_ + i0) * HD_;
    const __nv_bfloat16* kb  = k + (size_t)bh * N_ * HD_;
    const __nv_bfloat16* vb  = v + (size_t)bh * N_ * HD_;
    const __nv_bfloat16* pkb = posk + (size_t)h * TWO_PB * HD_;
    const __nv_bfloat16* pqb = posq + (size_t)h * TWO_PB * HD_;

    auto load_kv = [&](int j0, int p) {
        uint32_t dk = sb + A2_SK + p * 8192;
        uint32_t dv = sb + A2_SV + p * 8192;
        #pragma unroll
        for (int it = 0; it < 4; it++) {
            int c = it * 128 + tid, r = c >> 3, k8 = c & 7;
            uint32_t off = SWZ((uint32_t)(r * 128 + k8 * 16));
            CP_ASYNC16(dk + off, kb + (size_t)(j0 + r) * HD_ + k8 * 8);
            CP_ASYNC16(dv + off, vb + (size_t)(j0 + r) * HD_ + k8 * 8);
        }
    };
    auto load_pos = [&](int base) {
        #pragma unroll
        for (int it = 0; it < 8; it++) {
            int c = it * 128 + tid, r = c >> 3, k8 = c & 7;
            int sr = base + r; if (sr > 1023) sr = 1023;   // row 127 unused pad
            uint32_t off = SWZ((uint32_t)(r * 128 + k8 * 16));
            CP_ASYNC16(sPK + off, pkb + (size_t)sr * HD_ + k8 * 8);
            CP_ASYNC16(sPQ + off, pqb + (size_t)sr * HD_ + k8 * 8);
        }
    };

    // prologue: Q + first K/V + first pos, one group
    #pragma unroll
    for (int it = 0; it < 4; it++) {
        int c = it * 128 + tid, r = c >> 3, k8 = c & 7;
        CP_ASYNC16(sQ + SWZ((uint32_t)(r * 128 + k8 * 16)), qb + r * HD_ + k8 * 8);
    }
    load_kv(0, 0);
    load_pos(i0 + PB_ - 63);
    CP_COMMIT();

    float m0 = -INFINITY, m1 = -INFINITY, l0 = 0.f, l1 = 0.f;
    float opv[8][4];
    #pragma unroll
    for (int i = 0; i < 8; i++)
        #pragma unroll
        for (int e = 0; e < 4; e++) opv[i][e] = 0.f;
    const float inv_scale = 0.0721687836f;     // 1/sqrt(192)

    for (int jt = 0; jt < 8; jt++) {
        const int j0 = jt * 64;
        const int p = jt & 1;
        const uint32_t sKp = sb + A2_SK + p * 8192;
        const uint32_t sVp = sb + A2_SV + p * 8192;

        CP_WAIT0();
        __syncthreads();                       // loads for jt landed; prev iter fully done
        if (jt < 7) { load_kv(j0 + 64, p ^ 1); CP_COMMIT(); }

        // phase 1: band GEMMs C2P = Q.PKwin^T, P2C = K.PQwin^T
        #pragma unroll
        for (int ph = 0; ph < 2; ph++) {
            uint32_t aSrc = ph ? sKp : sQ;
            uint32_t bSrc = ph ? sPQ : sPK;
            uint32_t dSt  = ph ? sP : sC;
            float t[16][4];
            #pragma unroll
            for (int i = 0; i < 16; i++)
                #pragma unroll
                for (int e = 0; e < 4; e++) t[i][e] = 0.f;
            #pragma unroll
            for (int ks = 0; ks < 4; ks++) {
                uint32_t af[4];
                int ar = wm + (matm & 1) * 8 + rin, kc = ks * 16 + (matm >> 1) * 8;
                ldsm_x4(af, aSrc + SWZ((uint32_t)(ar * 128 + kc * 2)));
                #pragma unroll
                for (int u = 0; u < 8; u++) {
                    uint32_t bf4[4];
                    int nr = u * 16 + (matm & 1) * 8 + rin;
                    ldsm_x4(bf4, bSrc + SWZ((uint32_t)(nr * 128 + kc * 2)));
                    mma16816(t[2 * u],     af, bf4[0], bf4[2]);
                    mma16816(t[2 * u + 1], af, bf4[1], bf4[3]);
                }
            }
            #pragma unroll
            for (int nt = 0; nt < 16; nt++) {
                int col = nt * 8 + tg * 2;
                __nv_bfloat162 lo = __floats2bfloat162_rn(t[nt][0], t[nt][1]);
                __nv_bfloat162 hi = __floats2bfloat162_rn(t[nt][2], t[nt][3]);
                uint32_t a0 = dSt + (wm + g) * BAND_STRIDE + col * 2;
                uint32_t a1 = dSt + (wm + g + 8) * BAND_STRIDE + col * 2;
                asm volatile("st.shared.b32 [%0], %1;" :: "r"(a0), "r"(*(uint32_t*)&lo));
                asm volatile("st.shared.b32 [%0], %1;" :: "r"(a1), "r"(*(uint32_t*)&hi));
            }
        }
        __syncthreads();                       // bands visible; pos fully consumed
        if (jt < 7) { load_pos(i0 - (j0 + 64) + PB_ - 63); CP_COMMIT(); }

        // phase 2: S = Q.K^T + band gather, online softmax
        float s[8][4];
        #pragma unroll
        for (int i = 0; i < 8; i++)
            #pragma unroll
            for (int e = 0; e < 4; e++) s[i][e] = 0.f;
        #pragma unroll
        for (int ks = 0; ks < 4; ks++) {
            uint32_t af[4];
            int ar = wm + (matm & 1) * 8 + rin, kc = ks * 16 + (matm >> 1) * 8;
            ldsm_x4(af, sQ + SWZ((uint32_t)(ar * 128 + kc * 2)));
            #pragma unroll
            for (int u = 0; u < 4; u++) {
                uint32_t bf4[4];
                int nr = u * 16 + (matm & 1) * 8 + rin;
                ldsm_x4(bf4, sKp + SWZ((uint32_t)(nr * 128 + kc * 2)));
                mma16816(s[2 * u],     af, bf4[0], bf4[2]);
                mma16816(s[2 * u + 1], af, bf4[1], bf4[3]);
            }
        }
        #pragma unroll
        for (int nt = 0; nt < 8; nt++) {
            #pragma unroll
            for (int e = 0; e < 4; e++) {
                int di = wm + g + (e >> 1) * 8;
                int dj = nt * 8 + tg * 2 + (e & 1);
                int w = di - dj + 63;
                uint16_t cv, pv2;
                asm volatile("ld.shared.u16 %0, [%1];" : "=h"(cv)
                             : "r"(sC + di * BAND_STRIDE + w * 2));
                asm volatile("ld.shared.u16 %0, [%1];" : "=h"(pv2)
                             : "r"(sP + dj * BAND_STRIDE + w * 2));
                float add = __bfloat162float(*(__nv_bfloat16*)&cv)
                          + __bfloat162float(*(__nv_bfloat16*)&pv2);
                s[nt][e] = (s[nt][e] + add) * inv_scale;
            }
        }
        float mx0 = -INFINITY, mx1 = -INFINITY;
        #pragma unroll
        for (int nt = 0; nt < 8; nt++) {
            mx0 = fmaxf(mx0, fmaxf(s[nt][0], s[nt][1]));
            mx1 = fmaxf(mx1, fmaxf(s[nt][2], s[nt][3]));
        }
        mx0 = fmaxf(mx0, __shfl_xor_sync(0xFFFFFFFF, mx0, 1));
        mx0 = fmaxf(mx0, __shfl_xor_sync(0xFFFFFFFF, mx0, 2));
        mx1 = fmaxf(mx1, __shfl_xor_sync(0xFFFFFFFF, mx1, 1));
        mx1 = fmaxf(mx1, __shfl_xor_sync(0xFFFFFFFF, mx1, 2));
        float mn0 = fmaxf(m0, mx0), mn1 = fmaxf(m1, mx1);
        float sc0 = __expf(m0 - mn0), sc1 = __expf(m1 - mn1);
        m0 = mn0; m1 = mn1;
        float sum0 = 0.f, sum1 = 0.f;
        #pragma unroll
        for (int nt = 0; nt < 8; nt++) {
            #pragma unroll
            for (int e = 0; e < 4; e++) {
                float pr = __expf(s[nt][e] - ((e < 2) ? mn0 : mn1));
                s[nt][e] = pr;
                if (e < 2) sum0 += pr; else sum1 += pr;
            }
        }
        sum0 += __shfl_xor_sync(0xFFFFFFFF, sum0, 1);
        sum0 += __shfl_xor_sync(0xFFFFFFFF, sum0, 2);
        sum1 += __shfl_xor_sync(0xFFFFFFFF, sum1, 1);
        sum1 += __shfl_xor_sync(0xFFFFFFFF, sum1, 2);
        l0 = l0 * sc0 + sum0;
        l1 = l1 * sc1 + sum1;
        #pragma unroll
        for (int nt = 0; nt < 8; nt++) {
            opv[nt][0] *= sc0; opv[nt][1] *= sc0;
            opv[nt][2] *= sc1; opv[nt][3] *= sc1;
        }
        // PV: P (bf16 fragments) @ V via ldmatrix.trans
        #pragma unroll
        for (int kk = 0; kk < 4; kk++) {
            uint32_t aP[4];
            __nv_bfloat162 t0 = __floats2bfloat162_rn(s[2*kk][0],   s[2*kk][1]);
            __nv_bfloat162 t1 = __floats2bfloat162_rn(s[2*kk][2],   s[2*kk][3]);
            __nv_bfloat162 t2 = __floats2bfloat162_rn(s[2*kk+1][0], s[2*kk+1][1]);
            __nv_bfloat162 t3 = __floats2bfloat162_rn(s[2*kk+1][2], s[2*kk+1][3]);
            aP[0] = *(uint32_t*)&t0; aP[1] = *(uint32_t*)&t1;
            aP[2] = *(uint32_t*)&t2; aP[3] = *(uint32_t*)&t3;
            int jb = kk * 16;
            #pragma unroll
            for (int du = 0; du < 4; du++) {
                uint32_t bv[4];
                int vr = jb + (matm & 1) * 8 + rin, vc = du * 16 + (matm >> 1) * 8;
                ldsm_x4_t(bv, sVp + SWZ((uint32_t)(vr * 128 + vc * 2)));
                mma16816(opv[2 * du],     aP, bv[0], bv[1]);
                mma16816(opv[2 * du + 1], aP, bv[2], bv[3]);
            }
        }
        // no end-of-loop sync: top-of-loop barrier protects all reuse
    }

    const int b = bh >> 4;
    float il0 = 1.0f / l0, il1 = 1.0f / l1;
    int row0 = i0 + wm + g, row1 = row0 + 8;
    #pragma unroll
    for (int nt = 0; nt < 8; nt++) {
        int d = nt * 8 + tg * 2;
        __nv_bfloat162 o0 = __floats2bfloat162_rn(opv[nt][0] * il0, opv[nt][1] * il0);
        __nv_bfloat162 o1 = __floats2bfloat162_rn(opv[nt][2] * il1, opv[nt][3] * il1);
        *(__nv_bfloat162*)&ctx[(((size_t)b * N_ + row0) * H_ + h) * HD_ + d] = o0;
        *(__nv_bfloat162*)&ctx[(((size_t)b * N_ + row1) * H_ + h) * HD_ + d] = o1;
    }
}

// ---------------------------------------------------------------------------
// Row LayerNorm
// ---------------------------------------------------------------------------
__global__ __launch_bounds__(256) void ln_kernel(
    const float* __restrict__ hb, const float* __restrict__ gam,
    const float* __restrict__ bet, float* __restrict__ out)
{
    const int row = blockIdx.x, tid = threadIdx.x;
    const float* hr = hb + (size_t)row * D_;
    __shared__ float red[256];

    float lv[4];
    float s = 0.0f;
    #pragma unroll
    for (int i = 0; i < 4; i++) { lv[i] = hr[i*256 + tid]; s += lv[i]; }
    red[tid] = s; __syncthreads();
    #pragma unroll
    for (int o = 128; o > 0; o >>= 1) { if (tid < o) red[tid] += red[tid + o]; __syncthreads(); }
    float mu = red[0] * (1.0f / 1024.0f);
    __syncthreads();

    float s2 = 0.0f;
    #pragma unroll
    for (int i = 0; i < 4; i++) { float dv = lv[i] - mu; s2 += dv * dv; }
    red[tid] = s2; __syncthreads();
    #pragma unroll
    for (int o = 128; o > 0; o >>= 1) { if (tid < o) red[tid] += red[tid + o]; __syncthreads(); }
    float var = red[0] * (1.0f / 1024.0f);
    float inv = rsqrtf(var + 1e-7f);

    #pragma unroll
    for (int i = 0; i < 4; i++) {
        int c = i*256 + tid;
        out[(size_t)row * D_ + c] = (lv[i] - mu) * inv * gam[c] + bet[c];
    }
}

// ---------------------------------------------------------------------------
extern "C" void kernel_launch(void* const* d_in, const int* in_sizes, int n_in,
                              void* d_out, int out_size)
{
    const float* hidden = (const float*)d_in[0];
    const float* rel    = (const float*)d_in[1];
    const float* q_w = (const float*)d_in[2];  const float* q_b = (const float*)d_in[3];
    const float* k_w = (const float*)d_in[4];  const float* k_b = (const float*)d_in[5];
    const float* v_w = (const float*)d_in[6];  const float* v_b = (const float*)d_in[7];
    const float* pk_w = (const float*)d_in[8]; const float* pk_b = (const float*)d_in[9];
    const float* pq_w = (const float*)d_in[10];const float* pq_b = (const float*)d_in[11];
    const float* o_w = (const float*)d_in[12]; const float* o_b = (const float*)d_in[13];
    const float* ln_g = (const float*)d_in[14];const float* ln_b = (const float*)d_in[15];

    __nv_bfloat16 *pqb, *pkb, *pvb, *ppk, *ppq, *pctxbf, *phidbf, *prelbf, *pwbf;
    float *ph;
    cudaGetSymbolAddress((void**)&pqb,  g_qb);
    cudaGetSymbolAddress((void**)&pkb,  g_kb);
    cudaGetSymbolAddress((void**)&pvb,  g_vb);
    cudaGetSymbolAddress((void**)&ppk,  g_pkb);
    cudaGetSymbolAddress((void**)&ppq,  g_pqb);
    cudaGetSymbolAddress((void**)&pctxbf, g_ctx_bf);
    cudaGetSymbolAddress((void**)&ph,   g_h);
    cudaGetSymbolAddress((void**)&phidbf, g_hid_bf);
    cudaGetSymbolAddress((void**)&prelbf, g_rel_bf);
    cudaGetSymbolAddress((void**)&pwbf,   g_wbf);

    __nv_bfloat16* wq  = pwbf;                    // fused QKV base
    __nv_bfloat16* wpk = pwbf + 3ull * D_ * D_;   // fused pos base
    __nv_bfloat16* wo  = pwbf + 5ull * D_ * D_;

    cudaFuncSetAttribute(gemm_mma, cudaFuncAttributeMaxDynamicSharedMemorySize, GEMM_SMEM);
    cudaFuncSetAttribute(attn_mma, cudaFuncAttributeMaxDynamicSharedMemorySize, A2_SMEM);

    // fp32 -> bf16 conversions
    f2bf<<<BN_*D_/1024, 256>>>(hidden, phidbf, BN_*D_);
    f2bf<<<TWO_PB*D_/1024, 256>>>(rel, prelbf, TWO_PB*D_);
    f2bf6<<<dim3(D_*D_/1024, 6), 256>>>(q_w, k_w, v_w, pk_w, pq_w, o_w, pwbf);

    // fused QKV projection: one launch, N=3072
    gemm_mma<<<dim3(3*D_/128, BN_/128), 256, GEMM_SMEM>>>(
        phidbf, wq, q_b, k_b, v_b, nullptr, nullptr, 1);
    // fused pos projections: one launch, N=2048
    gemm_mma<<<dim3(2*D_/128, TWO_PB/128), 256, GEMM_SMEM>>>(
        prelbf, wpk, pk_b, pq_b, nullptr, nullptr, nullptr, 0);

    // tensorized disentangled flash attention -> bf16 ctx
    attn_mma<<<dim3(N_/64, B_*H_), 128, A2_SMEM>>>(pqb, pkb, pvb, ppk, ppq, pctxbf);

    // output projection + bias + residual (fp32 out)
    gemm_mma<<<dim3(D_/128, BN_/128), 256, GEMM_SMEM>>>(
        pctxbf, wo, o_b, o_b, o_b, hidden, ph, 2);

    // layernorm -> final output
    ln_kernel<<<BN_, 256>>>(ph, ln_g, ln_b, (float*)d_out);
}

// round 14
// speedup vs baseline: 1.1046x; 1.0673x over previous
#include <cuda_runtime.h>
#include <cuda_bf16.h>
#include <math.h>
#include <stdint.h>

#define H_   16
#define D_   1024
#define HD_  64
#define PB_  512
#define B_   8
#define N_   512
#define BN_  (B_*N_)          // 4096
#define TWO_PB (2*PB_)        // 1024

// ---------------- scratch (static device arrays: no allocation allowed) ----
__device__ __align__(16) __nv_bfloat16 g_qb[B_*H_*N_*HD_];     // [B,H,N,HD]
__device__ __align__(16) __nv_bfloat16 g_kb[B_*H_*N_*HD_];
__device__ __align__(16) __nv_bfloat16 g_vb[B_*H_*N_*HD_];
__device__ __align__(16) __nv_bfloat16 g_pkb[H_*TWO_PB*HD_];   // [H,2PB,HD]
__device__ __align__(16) __nv_bfloat16 g_pqb[H_*TWO_PB*HD_];
__device__ __align__(16) __nv_bfloat16 g_ctx_bf[BN_*D_];       // [B,N,H,HD]
__device__ float g_h[BN_*D_];                                  // pre-LN residual sum

__device__ __align__(16) __nv_bfloat16 g_hid_bf[BN_*D_];
__device__ __align__(16) __nv_bfloat16 g_rel_bf[TWO_PB*D_];
__device__ __align__(16) __nv_bfloat16 g_wbf[6][D_*D_];        // q,k,v,pk,pq,o (contiguous)

// ============================================================
// helpers (baseline sm_80+: ldmatrix, mma.sync, cp.async)
// ============================================================
__device__ __forceinline__ uint32_t smem_u32(const void* p) {
    uint32_t a;
    asm("{ .reg .u64 t; cvta.to.shared.u64 t, %1; cvt.u32.u64 %0, t; }"
        : "=r"(a) : "l"(p));
    return a;
}
__device__ __forceinline__ void ldsm_x4(uint32_t* r, uint32_t addr) {
    asm volatile("ldmatrix.sync.aligned.m8n8.x4.shared.b16 {%0,%1,%2,%3}, [%4];"
        : "=r"(r[0]), "=r"(r[1]), "=r"(r[2]), "=r"(r[3]) : "r"(addr));
}
__device__ __forceinline__ void ldsm_x4_t(uint32_t* r, uint32_t addr) {
    asm volatile("ldmatrix.sync.aligned.m8n8.x4.trans.shared.b16 {%0,%1,%2,%3}, [%4];"
        : "=r"(r[0]), "=r"(r[1]), "=r"(r[2]), "=r"(r[3]) : "r"(addr));
}
__device__ __forceinline__ void mma16816(float* c, const uint32_t* a, uint32_t b0, uint32_t b1) {
    asm volatile("mma.sync.aligned.m16n8k16.row.col.f32.bf16.bf16.f32 "
        "{%0,%1,%2,%3}, {%4,%5,%6,%7}, {%8,%9}, {%0,%1,%2,%3};"
        : "+f"(c[0]), "+f"(c[1]), "+f"(c[2]), "+f"(c[3])
        : "r"(a[0]), "r"(a[1]), "r"(a[2]), "r"(a[3]), "r"(b0), "r"(b1));
}
#define CP_ASYNC16(dst, src) \
    asm volatile("cp.async.cg.shared.global [%0], [%1], 16;" :: "r"(dst), "l"(src))
#define CP_COMMIT() asm volatile("cp.async.commit_group;" ::: "memory")
#define CP_WAIT0()  asm volatile("cp.async.wait_group 0;" ::: "memory")
#define CP_WAIT1()  asm volatile("cp.async.wait_group 1;" ::: "memory")

#define SWZ(off) ((off) ^ (((off) >> 3) & 0x70))

// ============================================================
// fp32 -> bf16 conversion kernels
// ============================================================
__global__ __launch_bounds__(256) void f2bf(const float* __restrict__ in,
                                            __nv_bfloat16* __restrict__ out, int n) {
    int i = (blockIdx.x * 256 + threadIdx.x) * 4;
    if (i < n) {
        float4 v = *(const float4*)(in + i);
        __nv_bfloat162 lo = __floats2bfloat162_rn(v.x, v.y);
        __nv_bfloat162 hi = __floats2bfloat162_rn(v.z, v.w);
        *(uint2*)(out + i) = make_uint2(*(uint32_t*)&lo, *(uint32_t*)&hi);
    }
}
__global__ __launch_bounds__(256) void f2bf6(
    const float* __restrict__ p0, const float* __restrict__ p1,
    const float* __restrict__ p2, const float* __restrict__ p3,
    const float* __restrict__ p4, const float* __restrict__ p5,
    __nv_bfloat16* __restrict__ out)
{
    const float* ps[6] = {p0, p1, p2, p3, p4, p5};
    const float* in = ps[blockIdx.y];
    int i = (blockIdx.x * 256 + threadIdx.x) * 4;
    float4 v = *(const float4*)(in + i);
    __nv_bfloat162 lo = __floats2bfloat162_rn(v.x, v.y);
    __nv_bfloat162 hi = __floats2bfloat162_rn(v.z, v.w);
    *(uint2*)(out + (size_t)blockIdx.y * D_ * D_ + i) = make_uint2(*(uint32_t*)&lo, *(uint32_t*)&hi);
}

// ============================================================
// mma.sync bf16 NT GEMM, 3-stage cp.async pipeline (R8 proven: 127 regs).
// out[m,c] = sum_k A[m,k]*W[c,k] + bias[c]; CTA tile 128x128, K-tile 64.
// mode 1: fused QKV (W rows [0,3072), t=bn>>10 selects g_qb/g_kb/g_vb + bias)
// mode 0: fused pos (W rows [0,2048), t selects g_pkb/g_pqb)
// mode 2: O proj + residual (fp32 out)
// ============================================================
#define KT 64
#define ABYTES (128*128)
#define STAGEBUF (2*ABYTES)          // A + B per stage = 32KB
#define GEMM_SMEM (3*STAGEBUF)       // 96KB

__global__ __launch_bounds__(256, 2) void gemm_mma(
    const __nv_bfloat16* __restrict__ A, const __nv_bfloat16* __restrict__ W,
    const float* __restrict__ b0p, const float* __restrict__ b1p,
    const float* __restrict__ b2p, const float* __restrict__ resid,
    float* __restrict__ outf, int mode)
{
    extern __shared__ char smch[];
    const uint32_t sbase = smem_u32(smch);
    const int tid = threadIdx.x, warp = tid >> 5, lane = tid & 31;
    const int bm = blockIdx.y * 128, bn = blockIdx.x * 128;
    const int wm = (warp >> 1) * 32, wn = (warp & 1) * 64;

    float acc[2][8][4];
    #pragma unroll
    for (int i = 0; i < 2; i++)
        #pragma unroll
        for (int j = 0; j < 8; j++)
            #pragma unroll
            for (int l = 0; l < 4; l++) acc[i][j][l] = 0.0f;

    auto load_tile = [&](int kt, int stage) {
        const __nv_bfloat16* Ap = A + (size_t)bm * D_ + kt * KT;
        const __nv_bfloat16* Wp = W + (size_t)bn * D_ + kt * KT;
        uint32_t da = sbase + stage * STAGEBUF;
        uint32_t db = da + ABYTES;
        #pragma unroll
        for (int i = 0; i < 4; i++) {
            int c = i * 256 + tid;
            int r = c >> 3, k8 = c & 7;
            uint32_t off = SWZ((uint32_t)(r * 128 + k8 * 16));
            CP_ASYNC16(da + off, Ap + (size_t)r * D_ + k8 * 8);
            CP_ASYNC16(db + off, Wp + (size_t)r * D_ + k8 * 8);
        }
    };

    load_tile(0, 0); CP_COMMIT();
    load_tile(1, 1); CP_COMMIT();

    const int matm = lane >> 3, rin = lane & 7;
    int stage = 0;
    for (int kt = 0; kt < 16; kt++) {
        if (kt == 15) CP_WAIT0(); else CP_WAIT1();
        __syncthreads();
        if (kt + 2 < 16) {
            int ns = stage + 2; if (ns >= 3) ns -= 3;
            load_tile(kt + 2, ns);
            CP_COMMIT();
        }
        uint32_t abase = sbase + stage * STAGEBUF;
        uint32_t bbase = abase + ABYTES;
        #pragma unroll
        for (int ks = 0; ks < 4; ks++) {
            uint32_t af[2][4], bfr[4][4];
            int kcol = ks * 16 + (matm >> 1) * 8;
            #pragma unroll
            for (int mt = 0; mt < 2; mt++) {
                int m = wm + mt * 16 + (matm & 1) * 8 + rin;
                ldsm_x4(af[mt], abase + SWZ((uint32_t)(m * 128 + kcol * 2)));
            }
            #pragma unroll
            for (int u = 0; u < 4; u++) {
                int n = wn + u * 16 + (matm & 1) * 8 + rin;
                ldsm_x4(bfr[u], bbase + SWZ((uint32_t)(n * 128 + kcol * 2)));
            }
            #pragma unroll
            for (int mt = 0; mt < 2; mt++)
                #pragma unroll
                for (int nt = 0; nt < 8; nt++) {
                    int u = nt >> 1, w = nt & 1;
                    mma16816(acc[mt][nt], af[mt], bfr[u][w], bfr[u][w + 2]);
                }
        }
        stage++; if (stage >= 3) stage -= 3;
    }

    // ---- epilogue ----
    const int g = lane >> 2, tg = lane & 3;
    const int t = bn >> 10;                         // which tensor (fused modes)
    const float* bias = (t == 0) ? b0p : ((t == 1) ? b1p : b2p);
    __nv_bfloat16* outbf = nullptr;
    if (mode == 1) outbf = (t == 0) ? g_qb : ((t == 1) ? g_kb : g_vb);
    else if (mode == 0) outbf = (t == 0) ? g_pkb : g_pqb;

    #pragma unroll
    for (int mt = 0; mt < 2; mt++) {
        #pragma unroll
        for (int nt = 0; nt < 8; nt++) {
            int col = bn + wn + nt * 8 + tg * 2;     // global col in fused N
            int cn = col & 1023;                      // col within tensor
            float bb0 = bias[cn], bb1 = bias[cn + 1];
            #pragma unroll
            for (int half = 0; half < 2; half++) {
                int m = bm + wm + mt * 16 + g + half * 8;
                float v0 = acc[mt][nt][half * 2 + 0] + bb0;
                float v1 = acc[mt][nt][half * 2 + 1] + bb1;
                if (mode == 2) {
                    size_t idx = (size_t)m * D_ + cn;
                    float2 r = *(const float2*)&resid[idx];
                    *(float2*)&outf[idx] = make_float2(v0 + r.x, v1 + r.y);
                } else {
                    __nv_bfloat162 pk2 = __floats2bfloat162_rn(v0, v1);
                    size_t idx;
                    int h = cn >> 6, hd = cn & 63;
                    if (mode == 1) {
                        int bb = m >> 9, n = m & 511;
                        idx = (((size_t)(bb * H_ + h)) * N_ + n) * HD_ + hd;
                    } else {
                        idx = ((size_t)h * TWO_PB + m) * HD_ + hd;
                    }
                    *(__nv_bfloat162*)&outbf[idx] = pk2;
                }
            }
        }
    }
}

// ============================================================
// Tensorized disentangled flash attention, pipelined loads.
// grid (N/64, B*H), 128 threads. K/V double-buffered; pos prefetched
// mid-iteration. Band GEMMs restricted to the 5 u-tiles per warp that
// the diagonal gather actually reads (saves 3/8 of band MMA work):
//   C2P warp w': u in [w', w'+4];  P2C warp w': u in [3-w', 7-w'].
// ============================================================
#define BAND_STRIDE 264
#define A2_SQ   0
#define A2_SK   8192                    // 2 x 8KB
#define A2_SV   24576                   // 2 x 8KB
#define A2_SPK  40960                   // 16KB
#define A2_SPQ  57344                   // 16KB
#define A2_SC   73728                   // band 64 x 264
#define A2_SP   (A2_SC + 64*BAND_STRIDE)
#define A2_SMEM (A2_SP + 64*BAND_STRIDE)   // 107520 B

__global__ __launch_bounds__(128) void attn_mma(
    const __nv_bfloat16* __restrict__ q, const __nv_bfloat16* __restrict__ k,
    const __nv_bfloat16* __restrict__ v, const __nv_bfloat16* __restrict__ posk,
    const __nv_bfloat16* __restrict__ posq, __nv_bfloat16* __restrict__ ctx)
{
    extern __shared__ char smch[];
    const uint32_t sb = smem_u32(smch);
    const uint32_t sQ = sb + A2_SQ;
    const uint32_t sPK = sb + A2_SPK, sPQ = sb + A2_SPQ;
    const uint32_t sC = sb + A2_SC, sP = sb + A2_SP;

    const int tid = threadIdx.x, warp = tid >> 5, lane = tid & 31;
    const int g = lane >> 2, tg = lane & 3;
    const int matm = lane >> 3, rin = lane & 7;
    const int wm = warp * 16;
    const int i0 = blockIdx.x * 64;
    const int bh = blockIdx.y;
    const int h = bh & (H_ - 1);

    const __nv_bfloat16* qb  = q + ((size_t)bh * N_ + i0) * HD_;
    const __nv_bfloat16* kb  = k + (size_t)bh * N_ * HD_;
    const __nv_bfloat16* vb  = v + (size_t)bh * N_ * HD_;
    const __nv_bfloat16* pkb = posk + (size_t)h * TWO_PB * HD_;
    const __nv_bfloat16* pqb = posq + (size_t)h * TWO_PB * HD_;

    auto load_kv = [&](int j0, int p) {
        uint32_t dk = sb + A2_SK + p * 8192;
        uint32_t dv = sb + A2_SV + p * 8192;
        #pragma unroll
        for (int it = 0; it < 4; it++) {
            int c = it * 128 + tid, r = c >> 3, k8 = c & 7;
            uint32_t off = SWZ((uint32_t)(r * 128 + k8 * 16));
            CP_ASYNC16(dk + off, kb + (size_t)(j0 + r) * HD_ + k8 * 8);
            CP_ASYNC16(dv + off, vb + (size_t)(j0 + r) * HD_ + k8 * 8);
        }
    };
    auto load_pos = [&](int base) {
        #pragma unroll
        for (int it = 0; it < 8; it++) {
            int c = it * 128 + tid, r = c >> 3, k8 = c & 7;
            int sr = base + r; if (sr > 1023) sr = 1023;   // row 127 unused pad
            uint32_t off = SWZ((uint32_t)(r * 128 + k8 * 16));
            CP_ASYNC16(sPK + off, pkb + (size_t)sr * HD_ + k8 * 8);
            CP_ASYNC16(sPQ + off, pqb + (size_t)sr * HD_ + k8 * 8);
        }
    };

    // prologue: Q + first K/V + first pos, one group
    #pragma unroll
    for (int it = 0; it < 4; it++) {
        int c = it * 128 + tid, r = c >> 3, k8 = c & 7;
        CP_ASYNC16(sQ + SWZ((uint32_t)(r * 128 + k8 * 16)), qb + r * HD_ + k8 * 8);
    }
    load_kv(0, 0);
    load_pos(i0 + PB_ - 63);
    CP_COMMIT();

    float m0 = -INFINITY, m1 = -INFINITY, l0 = 0.f, l1 = 0.f;
    float opv[8][4];
    #pragma unroll
    for (int i = 0; i < 8; i++)
        #pragma unroll
        for (int e = 0; e < 4; e++) opv[i][e] = 0.f;
    const float inv_scale = 0.0721687836f;     // 1/sqrt(192)

    for (int jt = 0; jt < 8; jt++) {
        const int j0 = jt * 64;
        const int p = jt & 1;
        const uint32_t sKp = sb + A2_SK + p * 8192;
        const uint32_t sVp = sb + A2_SV + p * 8192;

        CP_WAIT0();
        __syncthreads();                       // loads for jt landed; prev iter fully done
        if (jt < 7) { load_kv(j0 + 64, p ^ 1); CP_COMMIT(); }

        // phase 1: band GEMMs, restricted to 5 used u-tiles per warp
        #pragma unroll
        for (int ph = 0; ph < 2; ph++) {
            uint32_t aSrc = ph ? sKp : sQ;
            uint32_t bSrc = ph ? sPQ : sPK;
            uint32_t dSt  = ph ? sP : sC;
            const int ubase = ph ? (3 - warp) : warp;
            float t[10][4];
            #pragma unroll
            for (int i = 0; i < 10; i++)
                #pragma unroll
                for (int e = 0; e < 4; e++) t[i][e] = 0.f;
            #pragma unroll
            for (int ks = 0; ks < 4; ks++) {
                uint32_t af[4];
                int ar = wm + (matm & 1) * 8 + rin, kc = ks * 16 + (matm >> 1) * 8;
                ldsm_x4(af, aSrc + SWZ((uint32_t)(ar * 128 + kc * 2)));
                #pragma unroll
                for (int uu = 0; uu < 5; uu++) {
                    uint32_t bf4[4];
                    int nr = (ubase + uu) * 16 + (matm & 1) * 8 + rin;
                    ldsm_x4(bf4, bSrc + SWZ((uint32_t)(nr * 128 + kc * 2)));
                    mma16816(t[2 * uu],     af, bf4[0], bf4[2]);
                    mma16816(t[2 * uu + 1], af, bf4[1], bf4[3]);
                }
            }
            #pragma unroll
            for (int nt = 0; nt < 10; nt++) {
                int col = (ubase + (nt >> 1)) * 16 + (nt & 1) * 8 + tg * 2;
                __nv_bfloat162 lo = __floats2bfloat162_rn(t[nt][0], t[nt][1]);
                __nv_bfloat162 hi = __floats2bfloat162_rn(t[nt][2], t[nt][3]);
                uint32_t a0 = dSt + (wm + g) * BAND_STRIDE + col * 2;
                uint32_t a1 = dSt + (wm + g + 8) * BAND_STRIDE + col * 2;
                asm volatile("st.shared.b32 [%0], %1;" :: "r"(a0), "r"(*(uint32_t*)&lo));
                asm volatile("st.shared.b32 [%0], %1;" :: "r"(a1), "r"(*(uint32_t*)&hi));
            }
        }
        __syncthreads();                       // bands visible; pos fully consumed
        if (jt < 7) { load_pos(i0 - (j0 + 64) + PB_ - 63); CP_COMMIT(); }

        // phase 2: S = Q.K^T + band gather, online softmax
        float s[8][4];
        #pragma unroll
        for (int i = 0; i < 8; i++)
            #pragma unroll
            for (int e = 0; e < 4; e++) s[i][e] = 0.f;
        #pragma unroll
        for (int ks = 0; ks < 4; ks++) {
            uint32_t af[4];
            int ar = wm + (matm & 1) * 8 + rin, kc = ks * 16 + (matm >> 1) * 8;
            ldsm_x4(af, sQ + SWZ((uint32_t)(ar * 128 + kc * 2)));
            #pragma unroll
            for (int u = 0; u < 4; u++) {
                uint32_t bf4[4];
                int nr = u * 16 + (matm & 1) * 8 + rin;
                ldsm_x4(bf4, sKp + SWZ((uint32_t)(nr * 128 + kc * 2)));
                mma16816(s[2 * u],     af, bf4[0], bf4[2]);
                mma16816(s[2 * u + 1], af, bf4[1], bf4[3]);
            }
        }
        #pragma unroll
        for (int nt = 0; nt < 8; nt++) {
            #pragma unroll
            for (int e = 0; e < 4; e++) {
                int di = wm + g + (e >> 1) * 8;
                int dj = nt * 8 + tg * 2 + (e & 1);
                int w = di - dj + 63;
                uint16_t cv, pv2;
                asm volatile("ld.shared.u16 %0, [%1];" : "=h"(cv)
                             : "r"(sC + di * BAND_STRIDE + w * 2));
                asm volatile("ld.shared.u16 %0, [%1];" : "=h"(pv2)
                             : "r"(sP + dj * BAND_STRIDE + w * 2));
                float add = __bfloat162float(*(__nv_bfloat16*)&cv)
                          + __bfloat162float(*(__nv_bfloat16*)&pv2);
                s[nt][e] = (s[nt][e] + add) * inv_scale;
            }
        }
        float mx0 = -INFINITY, mx1 = -INFINITY;
        #pragma unroll
        for (int nt = 0; nt < 8; nt++) {
            mx0 = fmaxf(mx0, fmaxf(s[nt][0], s[nt][1]));
            mx1 = fmaxf(mx1, fmaxf(s[nt][2], s[nt][3]));
        }
        mx0 = fmaxf(mx0, __shfl_xor_sync(0xFFFFFFFF, mx0, 1));
        mx0 = fmaxf(mx0, __shfl_xor_sync(0xFFFFFFFF, mx0, 2));
        mx1 = fmaxf(mx1, __shfl_xor_sync(0xFFFFFFFF, mx1, 1));
        mx1 = fmaxf(mx1, __shfl_xor_sync(0xFFFFFFFF, mx1, 2));
        float mn0 = fmaxf(m0, mx0), mn1 = fmaxf(m1, mx1);
        float sc0 = __expf(m0 - mn0), sc1 = __expf(m1 - mn1);
        m0 = mn0; m1 = mn1;
        float sum0 = 0.f, sum1 = 0.f;
        #pragma unroll
        for (int nt = 0; nt < 8; nt++) {
            #pragma unroll
            for (int e = 0; e < 4; e++) {
                float pr = __expf(s[nt][e] - ((e < 2) ? mn0 : mn1));
                s[nt][e] = pr;
                if (e < 2) sum0 += pr; else sum1 += pr;
            }
        }
        sum0 += __shfl_xor_sync(0xFFFFFFFF, sum0, 1);
        sum0 += __shfl_xor_sync(0xFFFFFFFF, sum0, 2);
        sum1 += __shfl_xor_sync(0xFFFFFFFF, sum1, 1);
        sum1 += __shfl_xor_sync(0xFFFFFFFF, sum1, 2);
        l0 = l0 * sc0 + sum0;
        l1 = l1 * sc1 + sum1;
        #pragma unroll
        for (int nt = 0; nt < 8; nt++) {
            opv[nt][0] *= sc0; opv[nt][1] *= sc0;
            opv[nt][2] *= sc1; opv[nt][3] *= sc1;
        }
        // PV: P (bf16 fragments) @ V via ldmatrix.trans
        #pragma unroll
        for (int kk = 0; kk < 4; kk++) {
            uint32_t aP[4];
            __nv_bfloat162 t0 = __floats2bfloat162_rn(s[2*kk][0],   s[2*kk][1]);
            __nv_bfloat162 t1 = __floats2bfloat162_rn(s[2*kk][2],   s[2*kk][3]);
            __nv_bfloat162 t2 = __floats2bfloat162_rn(s[2*kk+1][0], s[2*kk+1][1]);
            __nv_bfloat162 t3 = __floats2bfloat162_rn(s[2*kk+1][2], s[2*kk+1][3]);
            aP[0] = *(uint32_t*)&t0; aP[1] = *(uint32_t*)&t1;
            aP[2] = *(uint32_t*)&t2; aP[3] = *(uint32_t*)&t3;
            int jb = kk * 16;
            #pragma unroll
            for (int du = 0; du < 4; du++) {
                uint32_t bv[4];
                int vr = jb + (matm & 1) * 8 + rin, vc = du * 16 + (matm >> 1) * 8;
                ldsm_x4_t(bv, sVp + SWZ((uint32_t)(vr * 128 + vc * 2)));
                mma16816(opv[2 * du],     aP, bv[0], bv[1]);
                mma16816(opv[2 * du + 1], aP, bv[2], bv[3]);
            }
        }
        // no end-of-loop sync: top-of-loop barrier protects all reuse
    }

    const int b = bh >> 4;
    float il0 = 1.0f / l0, il1 = 1.0f / l1;
    int row0 = i0 + wm + g, row1 = row0 + 8;
    #pragma unroll
    for (int nt = 0; nt < 8; nt++) {
        int d = nt * 8 + tg * 2;
        __nv_bfloat162 o0 = __floats2bfloat162_rn(opv[nt][0] * il0, opv[nt][1] * il0);
        __nv_bfloat162 o1 = __floats2bfloat162_rn(opv[nt][2] * il1, opv[nt][3] * il1);
        *(__nv_bfloat162*)&ctx[(((size_t)b * N_ + row0) * H_ + h) * HD_ + d] = o0;
        *(__nv_bfloat162*)&ctx[(((size_t)b * N_ + row1) * H_ + h) * HD_ + d] = o1;
    }
}

// ---------------------------------------------------------------------------
// Row LayerNorm
// ---------------------------------------------------------------------------
__global__ __launch_bounds__(256) void ln_kernel(
    const float* __restrict__ hb, const float* __restrict__ gam,
    const float* __restrict__ bet, float* __restrict__ out)
{
    const int row = blockIdx.x, tid = threadIdx.x;
    const float* hr = hb + (size_t)row * D_;
    __shared__ float red[256];

    float lv[4];
    float s = 0.0f;
    #pragma unroll
    for (int i = 0; i < 4; i++) { lv[i] = hr[i*256 + tid]; s += lv[i]; }
    red[tid] = s; __syncthreads();
    #pragma unroll
    for (int o = 128; o > 0; o >>= 1) { if (tid < o) red[tid] += red[tid + o]; __syncthreads(); }
    float mu = red[0] * (1.0f / 1024.0f);
    __syncthreads();

    float s2 = 0.0f;
    #pragma unroll
    for (int i = 0; i < 4; i++) { float dv = lv[i] - mu; s2 += dv * dv; }
    red[tid] = s2; __syncthreads();
    #pragma unroll
    for (int o = 128; o > 0; o >>= 1) { if (tid < o) red[tid] += red[tid + o]; __syncthreads(); }
    float var = red[0] * (1.0f / 1024.0f);
    float inv = rsqrtf(var + 1e-7f);

    #pragma unroll
    for (int i = 0; i < 4; i++) {
        int c = i*256 + tid;
        out[(size_t)row * D_ + c] = (lv[i] - mu) * inv * gam[c] + bet[c];
    }
}

// ---------------------------------------------------------------------------
extern "C" void kernel_launch(void* const* d_in, const int* in_sizes, int n_in,
                              void* d_out, int out_size)
{
    const float* hidden = (const float*)d_in[0];
    const float* rel    = (const float*)d_in[1];
    const float* q_w = (const float*)d_in[2];  const float* q_b = (const float*)d_in[3];
    const float* k_w = (const float*)d_in[4];  const float* k_b = (const float*)d_in[5];
    const float* v_w = (const float*)d_in[6];  const float* v_b = (const float*)d_in[7];
    const float* pk_w = (const float*)d_in[8]; const float* pk_b = (const float*)d_in[9];
    const float* pq_w = (const float*)d_in[10];const float* pq_b = (const float*)d_in[11];
    const float* o_w = (const float*)d_in[12]; const float* o_b = (const float*)d_in[13];
    const float* ln_g = (const float*)d_in[14];const float* ln_b = (const float*)d_in[15];

    __nv_bfloat16 *pqb, *pkb, *pvb, *ppk, *ppq, *pctxbf, *phidbf, *prelbf, *pwbf;
    float *ph;
    cudaGetSymbolAddress((void**)&pqb,  g_qb);
    cudaGetSymbolAddress((void**)&pkb,  g_kb);
    cudaGetSymbolAddress((void**)&pvb,  g_vb);
    cudaGetSymbolAddress((void**)&ppk,  g_pkb);
    cudaGetSymbolAddress((void**)&ppq,  g_pqb);
    cudaGetSymbolAddress((void**)&pctxbf, g_ctx_bf);
    cudaGetSymbolAddress((void**)&ph,   g_h);
    cudaGetSymbolAddress((void**)&phidbf, g_hid_bf);
    cudaGetSymbolAddress((void**)&prelbf, g_rel_bf);
    cudaGetSymbolAddress((void**)&pwbf,   g_wbf);

    __nv_bfloat16* wq  = pwbf;                    // fused QKV base
    __nv_bfloat16* wpk = pwbf + 3ull * D_ * D_;   // fused pos base
    __nv_bfloat16* wo  = pwbf + 5ull * D_ * D_;

    cudaFuncSetAttribute(gemm_mma, cudaFuncAttributeMaxDynamicSharedMemorySize, GEMM_SMEM);
    cudaFuncSetAttribute(attn_mma, cudaFuncAttributeMaxDynamicSharedMemorySize, A2_SMEM);

    // fp32 -> bf16 conversions
    f2bf<<<BN_*D_/1024, 256>>>(hidden, phidbf, BN_*D_);
    f2bf<<<TWO_PB*D_/1024, 256>>>(rel, prelbf, TWO_PB*D_);
    f2bf6<<<dim3(D_*D_/1024, 6), 256>>>(q_w, k_w, v_w, pk_w, pq_w, o_w, pwbf);

    // fused QKV projection: one launch, N=3072
    gemm_mma<<<dim3(3*D_/128, BN_/128), 256, GEMM_SMEM>>>(
        phidbf, wq, q_b, k_b, v_b, nullptr, nullptr, 1);
    // fused pos projections: one launch, N=2048
    gemm_mma<<<dim3(2*D_/128, TWO_PB/128), 256, GEMM_SMEM>>>(
        prelbf, wpk, pk_b, pq_b, nullptr, nullptr, nullptr, 0);

    // tensorized disentangled flash attention -> bf16 ctx
    attn_mma<<<dim3(N_/64, B_*H_), 128, A2_SMEM>>>(pqb, pkb, pvb, ppk, ppq, pctxbf);

    // output projection + bias + residual (fp32 out)
    gemm_mma<<<dim3(D_/128, BN_/128), 256, GEMM_SMEM>>>(
        pctxbf, wo, o_b, o_b, o_b, hidden, ph, 2);

    // layernorm -> final output
    ln_kernel<<<BN_, 256>>>(ph, ln_g, ln_b, (float*)d_out);
}

// round 15
// speedup vs baseline: 1.1128x; 1.0074x over previous
#include <cuda_runtime.h>
#include <cuda_bf16.h>
#include <math.h>
#include <stdint.h>

#define H_   16
#define D_   1024
#define HD_  64
#define PB_  512
#define B_   8
#define N_   512
#define BN_  (B_*N_)          // 4096
#define TWO_PB (2*PB_)        // 1024

// ---------------- scratch (static device arrays: no allocation allowed) ----
__device__ __align__(16) __nv_bfloat16 g_qb[B_*H_*N_*HD_];     // [B,H,N,HD]
__device__ __align__(16) __nv_bfloat16 g_kb[B_*H_*N_*HD_];
__device__ __align__(16) __nv_bfloat16 g_vb[B_*H_*N_*HD_];
__device__ __align__(16) __nv_bfloat16 g_pkb[H_*TWO_PB*HD_];   // [H,2PB,HD]
__device__ __align__(16) __nv_bfloat16 g_pqb[H_*TWO_PB*HD_];
__device__ __align__(16) __nv_bfloat16 g_ctx_bf[BN_*D_];       // [B,N,H,HD]
__device__ float g_h[BN_*D_];                                  // pre-LN residual sum

__device__ __align__(16) __nv_bfloat16 g_hid_bf[BN_*D_];
__device__ __align__(16) __nv_bfloat16 g_rel_bf[TWO_PB*D_];
__device__ __align__(16) __nv_bfloat16 g_wbf[6][D_*D_];        // q,k,v,pk,pq,o (contiguous)

// ============================================================
// helpers (baseline sm_80+: ldmatrix, mma.sync, cp.async)
// ============================================================
__device__ __forceinline__ uint32_t smem_u32(const void* p) {
    uint32_t a;
    asm("{ .reg .u64 t; cvta.to.shared.u64 t, %1; cvt.u32.u64 %0, t; }"
        : "=r"(a) : "l"(p));
    return a;
}
__device__ __forceinline__ void ldsm_x4(uint32_t* r, uint32_t addr) {
    asm volatile("ldmatrix.sync.aligned.m8n8.x4.shared.b16 {%0,%1,%2,%3}, [%4];"
        : "=r"(r[0]), "=r"(r[1]), "=r"(r[2]), "=r"(r[3]) : "r"(addr));
}
__device__ __forceinline__ void ldsm_x4_t(uint32_t* r, uint32_t addr) {
    asm volatile("ldmatrix.sync.aligned.m8n8.x4.trans.shared.b16 {%0,%1,%2,%3}, [%4];"
        : "=r"(r[0]), "=r"(r[1]), "=r"(r[2]), "=r"(r[3]) : "r"(addr));
}
__device__ __forceinline__ void mma16816(float* c, const uint32_t* a, uint32_t b0, uint32_t b1) {
    asm volatile("mma.sync.aligned.m16n8k16.row.col.f32.bf16.bf16.f32 "
        "{%0,%1,%2,%3}, {%4,%5,%6,%7}, {%8,%9}, {%0,%1,%2,%3};"
        : "+f"(c[0]), "+f"(c[1]), "+f"(c[2]), "+f"(c[3])
        : "r"(a[0]), "r"(a[1]), "r"(a[2]), "r"(a[3]), "r"(b0), "r"(b1));
}
#define CP_ASYNC16(dst, src) \
    asm volatile("cp.async.cg.shared.global [%0], [%1], 16;" :: "r"(dst), "l"(src))
#define CP_COMMIT() asm volatile("cp.async.commit_group;" ::: "memory")
#define CP_WAIT0()  asm volatile("cp.async.wait_group 0;" ::: "memory")
#define CP_WAIT1()  asm volatile("cp.async.wait_group 1;" ::: "memory")

#define SWZ(off) ((off) ^ (((off) >> 3) & 0x70))

// ============================================================
// fp32 -> bf16 conversion kernels
// ============================================================
__global__ __launch_bounds__(256) void f2bf(const float* __restrict__ in,
                                            __nv_bfloat16* __restrict__ out, int n) {
    int i = (blockIdx.x * 256 + threadIdx.x) * 4;
    if (i < n) {
        float4 v = *(const float4*)(in + i);
        __nv_bfloat162 lo = __floats2bfloat162_rn(v.x, v.y);
        __nv_bfloat162 hi = __floats2bfloat162_rn(v.z, v.w);
        *(uint2*)(out + i) = make_uint2(*(uint32_t*)&lo, *(uint32_t*)&hi);
    }
}
__global__ __launch_bounds__(256) void f2bf6(
    const float* __restrict__ p0, const float* __restrict__ p1,
    const float* __restrict__ p2, const float* __restrict__ p3,
    const float* __restrict__ p4, const float* __restrict__ p5,
    __nv_bfloat16* __restrict__ out)
{
    const float* ps[6] = {p0, p1, p2, p3, p4, p5};
    const float* in = ps[blockIdx.y];
    int i = (blockIdx.x * 256 + threadIdx.x) * 4;
    float4 v = *(const float4*)(in + i);
    __nv_bfloat162 lo = __floats2bfloat162_rn(v.x, v.y);
    __nv_bfloat162 hi = __floats2bfloat162_rn(v.z, v.w);
    *(uint2*)(out + (size_t)blockIdx.y * D_ * D_ + i) = make_uint2(*(uint32_t*)&lo, *(uint32_t*)&hi);
}

// ============================================================
// mma.sync bf16 NT GEMM, 3-stage cp.async pipeline (R8 proven: 127 regs).
// out[m,c] = sum_k A[m,k]*W[c,k] + bias[c]; CTA tile 128x128, K-tile 64.
// mode 1: fused QKV (W rows [0,3072), t=bn>>10 selects g_qb/g_kb/g_vb + bias)
// mode 0: fused pos (W rows [0,2048), t selects g_pkb/g_pqb)
// mode 2: O proj + residual (fp32 out)
// ============================================================
#define KT 64
#define ABYTES (128*128)
#define STAGEBUF (2*ABYTES)          // A + B per stage = 32KB
#define GEMM_SMEM (3*STAGEBUF)       // 96KB

__global__ __launch_bounds__(256, 2) void gemm_mma(
    const __nv_bfloat16* __restrict__ A, const __nv_bfloat16* __restrict__ W,
    const float* __restrict__ b0p, const float* __restrict__ b1p,
    const float* __restrict__ b2p, const float* __restrict__ resid,
    float* __restrict__ outf, int mode)
{
    extern __shared__ char smch[];
    const uint32_t sbase = smem_u32(smch);
    const int tid = threadIdx.x, warp = tid >> 5, lane = tid & 31;
    const int bm = blockIdx.y * 128, bn = blockIdx.x * 128;
    const int wm = (warp >> 1) * 32, wn = (warp & 1) * 64;

    float acc[2][8][4];
    #pragma unroll
    for (int i = 0; i < 2; i++)
        #pragma unroll
        for (int j = 0; j < 8; j++)
            #pragma unroll
            for (int l = 0; l < 4; l++) acc[i][j][l] = 0.0f;

    auto load_tile = [&](int kt, int stage) {
        const __nv_bfloat16* Ap = A + (size_t)bm * D_ + kt * KT;
        const __nv_bfloat16* Wp = W + (size_t)bn * D_ + kt * KT;
        uint32_t da = sbase + stage * STAGEBUF;
        uint32_t db = da + ABYTES;
        #pragma unroll
        for (int i = 0; i < 4; i++) {
            int c = i * 256 + tid;
            int r = c >> 3, k8 = c & 7;
            uint32_t off = SWZ((uint32_t)(r * 128 + k8 * 16));
            CP_ASYNC16(da + off, Ap + (size_t)r * D_ + k8 * 8);
            CP_ASYNC16(db + off, Wp + (size_t)r * D_ + k8 * 8);
        }
    };

    load_tile(0, 0); CP_COMMIT();
    load_tile(1, 1); CP_COMMIT();

    const int matm = lane >> 3, rin = lane & 7;
    int stage = 0;
    for (int kt = 0; kt < 16; kt++) {
        if (kt == 15) CP_WAIT0(); else CP_WAIT1();
        __syncthreads();
        if (kt + 2 < 16) {
            int ns = stage + 2; if (ns >= 3) ns -= 3;
            load_tile(kt + 2, ns);
            CP_COMMIT();
        }
        uint32_t abase = sbase + stage * STAGEBUF;
        uint32_t bbase = abase + ABYTES;
        #pragma unroll
        for (int ks = 0; ks < 4; ks++) {
            uint32_t af[2][4], bfr[4][4];
            int kcol = ks * 16 + (matm >> 1) * 8;
            #pragma unroll
            for (int mt = 0; mt < 2; mt++) {
                int m = wm + mt * 16 + (matm & 1) * 8 + rin;
                ldsm_x4(af[mt], abase + SWZ((uint32_t)(m * 128 + kcol * 2)));
            }
            #pragma unroll
            for (int u = 0; u < 4; u++) {
                int n = wn + u * 16 + (matm & 1) * 8 + rin;
                ldsm_x4(bfr[u], bbase + SWZ((uint32_t)(n * 128 + kcol * 2)));
            }
            #pragma unroll
            for (int mt = 0; mt < 2; mt++)
                #pragma unroll
                for (int nt = 0; nt < 8; nt++) {
                    int u = nt >> 1, w = nt & 1;
                    mma16816(acc[mt][nt], af[mt], bfr[u][w], bfr[u][w + 2]);
                }
        }
        stage++; if (stage >= 3) stage -= 3;
    }

    // ---- epilogue ----
    const int g = lane >> 2, tg = lane & 3;
    const int t = bn >> 10;                         // which tensor (fused modes)
    const float* bias = (t == 0) ? b0p : ((t == 1) ? b1p : b2p);
    __nv_bfloat16* outbf = nullptr;
    if (mode == 1) outbf = (t == 0) ? g_qb : ((t == 1) ? g_kb : g_vb);
    else if (mode == 0) outbf = (t == 0) ? g_pkb : g_pqb;

    #pragma unroll
    for (int mt = 0; mt < 2; mt++) {
        #pragma unroll
        for (int nt = 0; nt < 8; nt++) {
            int col = bn + wn + nt * 8 + tg * 2;     // global col in fused N
            int cn = col & 1023;                      // col within tensor
            float bb0 = bias[cn], bb1 = bias[cn + 1];
            #pragma unroll
            for (int half = 0; half < 2; half++) {
                int m = bm + wm + mt * 16 + g + half * 8;
                float v0 = acc[mt][nt][half * 2 + 0] + bb0;
                float v1 = acc[mt][nt][half * 2 + 1] + bb1;
                if (mode == 2) {
                    size_t idx = (size_t)m * D_ + cn;
                    float2 r = *(const float2*)&resid[idx];
                    *(float2*)&outf[idx] = make_float2(v0 + r.x, v1 + r.y);
                } else {
                    __nv_bfloat162 pk2 = __floats2bfloat162_rn(v0, v1);
                    size_t idx;
                    int h = cn >> 6, hd = cn & 63;
                    if (mode == 1) {
                        int bb = m >> 9, n = m & 511;
                        idx = (((size_t)(bb * H_ + h)) * N_ + n) * HD_ + hd;
                    } else {
                        idx = ((size_t)h * TWO_PB + m) * HD_ + hd;
                    }
                    *(__nv_bfloat162*)&outbf[idx] = pk2;
                }
            }
        }
    }
}

// ============================================================
// Tensorized disentangled flash attention, pipelined loads.
// grid (N/64, B*H), 128 threads. K/V double-buffered.
// PK/PQ held in a 128-row RING buffer (slot = row & 127): consecutive
// j-windows overlap by 63 rows, so steady-state loads only 64 new rows
// (16KB/iter vs 32KB). Disjointness: next window keeps rows
// [base, base+62] (slots base..base+62 mod 128) while prefetch writes
// rows [base-64, base-1] (slots base-64..base-1 mod 128) — disjoint.
// Band GEMMs restricted to the 5 u-tiles/warp the gather reads.
// ============================================================
#define BAND_STRIDE 264
#define A2_SQ   0
#define A2_SK   8192                    // 2 x 8KB
#define A2_SV   24576                   // 2 x 8KB
#define A2_SPK  40960                   // 16KB ring (128 rows)
#define A2_SPQ  57344                   // 16KB ring
#define A2_SC   73728                   // band 64 x 264
#define A2_SP   (A2_SC + 64*BAND_STRIDE)
#define A2_SMEM (A2_SP + 64*BAND_STRIDE)   // 107520 B

__global__ __launch_bounds__(128) void attn_mma(
    const __nv_bfloat16* __restrict__ q, const __nv_bfloat16* __restrict__ k,
    const __nv_bfloat16* __restrict__ v, const __nv_bfloat16* __restrict__ posk,
    const __nv_bfloat16* __restrict__ posq, __nv_bfloat16* __restrict__ ctx)
{
    extern __shared__ char smch[];
    const uint32_t sb = smem_u32(smch);
    const uint32_t sQ = sb + A2_SQ;
    const uint32_t sPK = sb + A2_SPK, sPQ = sb + A2_SPQ;
    const uint32_t sC = sb + A2_SC, sP = sb + A2_SP;

    const int tid = threadIdx.x, warp = tid >> 5, lane = tid & 31;
    const int g = lane >> 2, tg = lane & 3;
    const int matm = lane >> 3, rin = lane & 7;
    const int wm = warp * 16;
    const int i0 = blockIdx.x * 64;
    const int bh = blockIdx.y;
    const int h = bh & (H_ - 1);

    const __nv_bfloat16* qb  = q + ((size_t)bh * N_ + i0) * HD_;
    const __nv_bfloat16* kb  = k + (size_t)bh * N_ * HD_;
    const __nv_bfloat16* vb  = v + (size_t)bh * N_ * HD_;
    const __nv_bfloat16* pkb = posk + (size_t)h * TWO_PB * HD_;
    const __nv_bfloat16* pqb = posq + (size_t)h * TWO_PB * HD_;

    auto load_kv = [&](int j0, int p) {
        uint32_t dk = sb + A2_SK + p * 8192;
        uint32_t dv = sb + A2_SV + p * 8192;
        #pragma unroll
        for (int it = 0; it < 4; it++) {
            int c = it * 128 + tid, r = c >> 3, k8 = c & 7;
            uint32_t off = SWZ((uint32_t)(r * 128 + k8 * 16));
            CP_ASYNC16(dk + off, kb + (size_t)(j0 + r) * HD_ + k8 * 8);
            CP_ASYNC16(dv + off, vb + (size_t)(j0 + r) * HD_ + k8 * 8);
        }
    };
    // ring loader: rows [rbase, rbase+nrows) into slot (row & 127)
    auto load_pos = [&](int rbase, int nit) {
        for (int it = 0; it < nit; it++) {
            int c = it * 128 + tid, r = c >> 3, k8 = c & 7;
            int sr = rbase + r; if (sr > 1023) sr = 1023;
            uint32_t off = SWZ((uint32_t)(((sr & 127) * 128) + k8 * 16));
            CP_ASYNC16(sPK + off, pkb + (size_t)sr * HD_ + k8 * 8);
            CP_ASYNC16(sPQ + off, pqb + (size_t)sr * HD_ + k8 * 8);
        }
    };

    // prologue: Q + first K/V + full first pos window (128 rows), one group
    #pragma unroll
    for (int it = 0; it < 4; it++) {
        int c = it * 128 + tid, r = c >> 3, k8 = c & 7;
        CP_ASYNC16(sQ + SWZ((uint32_t)(r * 128 + k8 * 16)), qb + r * HD_ + k8 * 8);
    }
    load_kv(0, 0);
    load_pos(i0 + PB_ - 63, 8);
    CP_COMMIT();

    float m0 = -INFINITY, m1 = -INFINITY, l0 = 0.f, l1 = 0.f;
    float opv[8][4];
    #pragma unroll
    for (int i = 0; i < 8; i++)
        #pragma unroll
        for (int e = 0; e < 4; e++) opv[i][e] = 0.f;
    const float inv_scale = 0.0721687836f;     // 1/sqrt(192)

    for (int jt = 0; jt < 8; jt++) {
        const int j0 = jt * 64;
        const int p = jt & 1;
        const uint32_t sKp = sb + A2_SK + p * 8192;
        const uint32_t sVp = sb + A2_SV + p * 8192;
        const int base = i0 - j0 + PB_ - 63;   // window start, in [1, 897]

        CP_WAIT0();
        __syncthreads();                       // loads for jt landed; prev iter fully done
        if (jt < 7) { load_kv(j0 + 64, p ^ 1); CP_COMMIT(); }

        // phase 1: band GEMMs, restricted to 5 used u-tiles per warp
        #pragma unroll
        for (int ph = 0; ph < 2; ph++) {
            uint32_t aSrc = ph ? sKp : sQ;
            uint32_t bSrc = ph ? sPQ : sPK;
            uint32_t dSt  = ph ? sP : sC;
            const int ubase = ph ? (3 - warp) : warp;
            float t[10][4];
            #pragma unroll
            for (int i = 0; i < 10; i++)
                #pragma unroll
                for (int e = 0; e < 4; e++) t[i][e] = 0.f;
            #pragma unroll
            for (int ks = 0; ks < 4; ks++) {
                uint32_t af[4];
                int ar = wm + (matm & 1) * 8 + rin, kc = ks * 16 + (matm >> 1) * 8;
                ldsm_x4(af, aSrc + SWZ((uint32_t)(ar * 128 + kc * 2)));
                #pragma unroll
                for (int uu = 0; uu < 5; uu++) {
                    uint32_t bf4[4];
                    int nr = (ubase + uu) * 16 + (matm & 1) * 8 + rin;
                    int slot = (base + nr) & 127;
                    ldsm_x4(bf4, bSrc + SWZ((uint32_t)(slot * 128 + kc * 2)));
                    mma16816(t[2 * uu],     af, bf4[0], bf4[2]);
                    mma16816(t[2 * uu + 1], af, bf4[1], bf4[3]);
                }
            }
            #pragma unroll
            for (int nt = 0; nt < 10; nt++) {
                int col = (ubase + (nt >> 1)) * 16 + (nt & 1) * 8 + tg * 2;
                __nv_bfloat162 lo = __floats2bfloat162_rn(t[nt][0], t[nt][1]);
                __nv_bfloat162 hi = __floats2bfloat162_rn(t[nt][2], t[nt][3]);
                uint32_t a0 = dSt + (wm + g) * BAND_STRIDE + col * 2;
                uint32_t a1 = dSt + (wm + g + 8) * BAND_STRIDE + col * 2;
                asm volatile("st.shared.b32 [%0], %1;" :: "r"(a0), "r"(*(uint32_t*)&lo));
                asm volatile("st.shared.b32 [%0], %1;" :: "r"(a1), "r"(*(uint32_t*)&hi));
            }
        }
        __syncthreads();                       // bands visible; pos fully consumed
        if (jt < 7) { load_pos(base - 64, 4); CP_COMMIT(); }   // 64 new ring rows

        // phase 2: S = Q.K^T + band gather, online softmax
        float s[8][4];
        #pragma unroll
        for (int i = 0; i < 8; i++)
            #pragma unroll
            for (int e = 0; e < 4; e++) s[i][e] = 0.f;
        #pragma unroll
        for (int ks = 0; ks < 4; ks++) {
            uint32_t af[4];
            int ar = wm + (matm & 1) * 8 + rin, kc = ks * 16 + (matm >> 1) * 8;
            ldsm_x4(af, sQ + SWZ((uint32_t)(ar * 128 + kc * 2)));
            #pragma unroll
            for (int u = 0; u < 4; u++) {
                uint32_t bf4[4];
                int nr = u * 16 + (matm & 1) * 8 + rin;
                ldsm_x4(bf4, sKp + SWZ((uint32_t)(nr * 128 + kc * 2)));
                mma16816(s[2 * u],     af, bf4[0], bf4[2]);
                mma16816(s[2 * u + 1], af, bf4[1], bf4[3]);
            }
        }
        #pragma unroll
        for (int nt = 0; nt < 8; nt++) {
            #pragma unroll
            for (int e = 0; e < 4; e++) {
                int di = wm + g + (e >> 1) * 8;
                int dj = nt * 8 + tg * 2 + (e & 1);
                int w = di - dj + 63;
                uint16_t cv, pv2;
                asm volatile("ld.shared.u16 %0, [%1];" : "=h"(cv)
                             : "r"(sC + di * BAND_STRIDE + w * 2));
                asm volatile("ld.shared.u16 %0, [%1];" : "=h"(pv2)
                             : "r"(sP + dj * BAND_STRIDE + w * 2));
                float add = __bfloat162float(*(__nv_bfloat16*)&cv)
                          + __bfloat162float(*(__nv_bfloat16*)&pv2);
                s[nt][e] = (s[nt][e] + add) * inv_scale;
            }
        }
        float mx0 = -INFINITY, mx1 = -INFINITY;
        #pragma unroll
        for (int nt = 0; nt < 8; nt++) {
            mx0 = fmaxf(mx0, fmaxf(s[nt][0], s[nt][1]));
            mx1 = fmaxf(mx1, fmaxf(s[nt][2], s[nt][3]));
        }
        mx0 = fmaxf(mx0, __shfl_xor_sync(0xFFFFFFFF, mx0, 1));
        mx0 = fmaxf(mx0, __shfl_xor_sync(0xFFFFFFFF, mx0, 2));
        mx1 = fmaxf(mx1, __shfl_xor_sync(0xFFFFFFFF, mx1, 1));
        mx1 = fmaxf(mx1, __shfl_xor_sync(0xFFFFFFFF, mx1, 2));
        float mn0 = fmaxf(m0, mx0), mn1 = fmaxf(m1, mx1);
        float sc0 = __expf(m0 - mn0), sc1 = __expf(m1 - mn1);
        m0 = mn0; m1 = mn1;
        float sum0 = 0.f, sum1 = 0.f;
        #pragma unroll
        for (int nt = 0; nt < 8; nt++) {
            #pragma unroll
            for (int e = 0; e < 4; e++) {
                float pr = __expf(s[nt][e] - ((e < 2) ? mn0 : mn1));
                s[nt][e] = pr;
                if (e < 2) sum0 += pr; else sum1 += pr;
            }
        }
        sum0 += __shfl_xor_sync(0xFFFFFFFF, sum0, 1);
        sum0 += __shfl_xor_sync(0xFFFFFFFF, sum0, 2);
        sum1 += __shfl_xor_sync(0xFFFFFFFF, sum1, 1);
        sum1 += __shfl_xor_sync(0xFFFFFFFF, sum1, 2);
        l0 = l0 * sc0 + sum0;
        l1 = l1 * sc1 + sum1;
        #pragma unroll
        for (int nt = 0; nt < 8; nt++) {
            opv[nt][0] *= sc0; opv[nt][1] *= sc0;
            opv[nt][2] *= sc1; opv[nt][3] *= sc1;
        }
        // PV: P (bf16 fragments) @ V via ldmatrix.trans
        #pragma unroll
        for (int kk = 0; kk < 4; kk++) {
            uint32_t aP[4];
            __nv_bfloat162 t0 = __floats2bfloat162_rn(s[2*kk][0],   s[2*kk][1]);
            __nv_bfloat162 t1 = __floats2bfloat162_rn(s[2*kk][2],   s[2*kk][3]);
            __nv_bfloat162 t2 = __floats2bfloat162_rn(s[2*kk+1][0], s[2*kk+1][1]);
            __nv_bfloat162 t3 = __floats2bfloat162_rn(s[2*kk+1][2], s[2*kk+1][3]);
            aP[0] = *(uint32_t*)&t0; aP[1] = *(uint32_t*)&t1;
            aP[2] = *(uint32_t*)&t2; aP[3] = *(uint32_t*)&t3;
            int jb = kk * 16;
            #pragma unroll
            for (int du = 0; du < 4; du++) {
                uint32_t bv[4];
                int vr = jb + (matm & 1) * 8 + rin, vc = du * 16 + (matm >> 1) * 8;
                ldsm_x4_t(bv, sVp + SWZ((uint32_t)(vr * 128 + vc * 2)));
                mma16816(opv[2 * du],     aP, bv[0], bv[1]);
                mma16816(opv[2 * du + 1], aP, bv[2], bv[3]);
            }
        }
        // no end-of-loop sync: top-of-loop barrier protects all reuse
    }

    const int b = bh >> 4;
    float il0 = 1.0f / l0, il1 = 1.0f / l1;
    int row0 = i0 + wm + g, row1 = row0 + 8;
    #pragma unroll
    for (int nt = 0; nt < 8; nt++) {
        int d = nt * 8 + tg * 2;
        __nv_bfloat162 o0 = __floats2bfloat162_rn(opv[nt][0] * il0, opv[nt][1] * il0);
        __nv_bfloat162 o1 = __floats2bfloat162_rn(opv[nt][2] * il1, opv[nt][3] * il1);
        *(__nv_bfloat162*)&ctx[(((size_t)b * N_ + row0) * H_ + h) * HD_ + d] = o0;
        *(__nv_bfloat162*)&ctx[(((size_t)b * N_ + row1) * H_ + h) * HD_ + d] = o1;
    }
}

// ---------------------------------------------------------------------------
// Row LayerNorm
// ---------------------------------------------------------------------------
__global__ __launch_bounds__(256) void ln_kernel(
    const float* __restrict__ hb, const float* __restrict__ gam,
    const float* __restrict__ bet, float* __restrict__ out)
{
    const int row = blockIdx.x, tid = threadIdx.x;
    const float* hr = hb + (size_t)row * D_;
    __shared__ float red[256];

    float lv[4];
    float s = 0.0f;
    #pragma unroll
    for (int i = 0; i < 4; i++) { lv[i] = hr[i*256 + tid]; s += lv[i]; }
    red[tid] = s; __syncthreads();
    #pragma unroll
    for (int o = 128; o > 0; o >>= 1) { if (tid < o) red[tid] += red[tid + o]; __syncthreads(); }
    float mu = red[0] * (1.0f / 1024.0f);
    __syncthreads();

    float s2 = 0.0f;
    #pragma unroll
    for (int i = 0; i < 4; i++) { float dv = lv[i] - mu; s2 += dv * dv; }
    red[tid] = s2; __syncthreads();
    #pragma unroll
    for (int o = 128; o > 0; o >>= 1) { if (tid < o) red[tid] += red[tid + o]; __syncthreads(); }
    float var = red[0] * (1.0f / 1024.0f);
    float inv = rsqrtf(var + 1e-7f);

    #pragma unroll
    for (int i = 0; i < 4; i++) {
        int c = i*256 + tid;
        out[(size_t)row * D_ + c] = (lv[i] - mu) * inv * gam[c] + bet[c];
    }
}

// ---------------------------------------------------------------------------
extern "C" void kernel_launch(void* const* d_in, const int* in_sizes, int n_in,
                              void* d_out, int out_size)
{
    const float* hidden = (const float*)d_in[0];
    const float* rel    = (const float*)d_in[1];
    const float* q_w = (const float*)d_in[2];  const float* q_b = (const float*)d_in[3];
    const float* k_w = (const float*)d_in[4];  const float* k_b = (const float*)d_in[5];
    const float* v_w = (const float*)d_in[6];  const float* v_b = (const float*)d_in[7];
    const float* pk_w = (const float*)d_in[8]; const float* pk_b = (const float*)d_in[9];
    const float* pq_w = (const float*)d_in[10];const float* pq_b = (const float*)d_in[11];
    const float* o_w = (const float*)d_in[12]; const float* o_b = (const float*)d_in[13];
    const float* ln_g = (const float*)d_in[14];const float* ln_b = (const float*)d_in[15];

    __nv_bfloat16 *pqb, *pkb, *pvb, *ppk, *ppq, *pctxbf, *phidbf, *prelbf, *pwbf;
    float *ph;
    cudaGetSymbolAddress((void**)&pqb,  g_qb);
    cudaGetSymbolAddress((void**)&pkb,  g_kb);
    cudaGetSymbolAddress((void**)&pvb,  g_vb);
    cudaGetSymbolAddress((void**)&ppk,  g_pkb);
    cudaGetSymbolAddress((void**)&ppq,  g_pqb);
    cudaGetSymbolAddress((void**)&pctxbf, g_ctx_bf);
    cudaGetSymbolAddress((void**)&ph,   g_h);
    cudaGetSymbolAddress((void**)&phidbf, g_hid_bf);
    cudaGetSymbolAddress((void**)&prelbf, g_rel_bf);
    cudaGetSymbolAddress((void**)&pwbf,   g_wbf);

    __nv_bfloat16* wq  = pwbf;                    // fused QKV base
    __nv_bfloat16* wpk = pwbf + 3ull * D_ * D_;   // fused pos base
    __nv_bfloat16* wo  = pwbf + 5ull * D_ * D_;

    cudaFuncSetAttribute(gemm_mma, cudaFuncAttributeMaxDynamicSharedMemorySize, GEMM_SMEM);
    cudaFuncSetAttribute(attn_mma, cudaFuncAttributeMaxDynamicSharedMemorySize, A2_SMEM);

    // fp32 -> bf16 conversions
    f2bf<<<BN_*D_/1024, 256>>>(hidden, phidbf, BN_*D_);
    f2bf<<<TWO_PB*D_/1024, 256>>>(rel, prelbf, TWO_PB*D_);
    f2bf6<<<dim3(D_*D_/1024, 6), 256>>>(q_w, k_w, v_w, pk_w, pq_w, o_w, pwbf);

    // fused QKV projection: one launch, N=3072
    gemm_mma<<<dim3(3*D_/128, BN_/128), 256, GEMM_SMEM>>>(
        phidbf, wq, q_b, k_b, v_b, nullptr, nullptr, 1);
    // fused pos projections: one launch, N=2048
    gemm_mma<<<dim3(2*D_/128, TWO_PB/128), 256, GEMM_SMEM>>>(
        prelbf, wpk, pk_b, pq_b, nullptr, nullptr, nullptr, 0);

    // tensorized disentangled flash attention -> bf16 ctx
    attn_mma<<<dim3(N_/64, B_*H_), 128, A2_SMEM>>>(pqb, pkb, pvb, ppk, ppq, pctxbf);

    // output projection + bias + residual (fp32 out)
    gemm_mma<<<dim3(D_/128, BN_/128), 256, GEMM_SMEM>>>(
        pctxbf, wo, o_b, o_b, o_b, hidden, ph, 2);

    // layernorm -> final output
    ln_kernel<<<BN_, 256>>>(ph, ln_g, ln_b, (float*)d_out);
}